// round 11
// baseline (speedup 1.0000x reference)
#include <cuda_runtime.h>
#include <cuda_fp16.h>
#include <cstdint>

#define BB 4
#define TT 2048
#define SS 2048
#define CC 1024
#define HH 16
#define DD 64
#define SCALE_F 0.125f
#define MT (BB * TT)

typedef unsigned long long u64;
typedef unsigned int u32;
typedef unsigned short u16;

// ---------------------------------------------------------------------------
// Scratch (allocation-free rule: __device__ globals)
// ---------------------------------------------------------------------------
__device__ u16 g_xh[3][MT * CC];           // input splits (q,k,v) bf16 hi
__device__ u16 g_xl[3][MT * CC];           // bf16 lo
__device__ u16 g_wh[4][CC * CC];           // weight splits (q,k,v,out) bf16 hi
__device__ u16 g_wl[4][CC * CC];
__device__ u16 g_ph[3][BB * HH * TT * DD]; // projected q,k,v f16 hi (B,H,T,D)
__device__ u16 g_pl[3][BB * HH * TT * DD]; // f16 lo
__device__ u16 g_ah[MT * CC];              // attn out bf16 hi (B,T,C)
__device__ u16 g_al[MT * CC];
__device__ int g_flags;                    // bit0: mask nonzero, bit1: kpm any

// ---------------------------------------------------------------------------
// helpers
// ---------------------------------------------------------------------------
__device__ __forceinline__ u32 smem_u32(const void* p) {
    u32 a;
    asm("{ .reg .u64 t; cvta.to.shared.u64 t, %1; cvt.u32.u64 %0, t; }" : "=r"(a) : "l"(p));
    return a;
}
__device__ __forceinline__ void ldsm4(u32 addr, u32* r) {
    asm volatile("ldmatrix.sync.aligned.m8n8.x4.shared.b16 {%0,%1,%2,%3},[%4];"
                 : "=r"(r[0]), "=r"(r[1]), "=r"(r[2]), "=r"(r[3]) : "r"(addr));
}
__device__ __forceinline__ void ldsm4t(u32 addr, u32* r) {
    asm volatile("ldmatrix.sync.aligned.m8n8.x4.trans.shared.b16 {%0,%1,%2,%3},[%4];"
                 : "=r"(r[0]), "=r"(r[1]), "=r"(r[2]), "=r"(r[3]) : "r"(addr));
}
__device__ __forceinline__ void mma_bf(float* c, const u32* a, const u32* b) {
    asm volatile(
        "mma.sync.aligned.m16n8k16.row.col.f32.bf16.bf16.f32 "
        "{%0,%1,%2,%3},{%4,%5,%6,%7},{%8,%9},{%0,%1,%2,%3};"
        : "+f"(c[0]), "+f"(c[1]), "+f"(c[2]), "+f"(c[3])
        : "r"(a[0]), "r"(a[1]), "r"(a[2]), "r"(a[3]), "r"(b[0]), "r"(b[1]));
}
__device__ __forceinline__ void mma_f16(float* c, const u32* a, const u32* b) {
    asm volatile(
        "mma.sync.aligned.m16n8k16.row.col.f32.f16.f16.f32 "
        "{%0,%1,%2,%3},{%4,%5,%6,%7},{%8,%9},{%0,%1,%2,%3};"
        : "+f"(c[0]), "+f"(c[1]), "+f"(c[2]), "+f"(c[3])
        : "r"(a[0]), "r"(a[1]), "r"(a[2]), "r"(a[3]), "r"(b[0]), "r"(b[1]));
}
__device__ __forceinline__ u32 f16pair(float lo, float hi) {
    u32 r; asm("cvt.rn.f16x2.f32 %0,%1,%2;" : "=r"(r) : "f"(hi), "f"(lo)); return r;
}
__device__ __forceinline__ void h2unpack(u32 v, float& lo, float& hi) {
    asm("{.reg .b16 l,h; mov.b32 {l,h}, %2; cvt.f32.f16 %0, l; cvt.f32.f16 %1, h;}"
        : "=f"(lo), "=f"(hi) : "r"(v));
}
__device__ __forceinline__ void cpa16(u32 dst, const void* src) {
    asm volatile("cp.async.cg.shared.global [%0], [%1], 16;" :: "r"(dst), "l"(src));
}
__device__ __forceinline__ void cpa_commit() {
    asm volatile("cp.async.commit_group;" ::: "memory");
}
template <int N>
__device__ __forceinline__ void cpa_wait() {
    asm volatile("cp.async.wait_group %0;" :: "n"(N) : "memory");
}
// bf16 split: hi = truncation (exact), lo = rn(x - hi)
__device__ __forceinline__ void split2_bf16(float x, float y, u32& hi, u32& lo) {
    u32 ax = __float_as_uint(x), ay = __float_as_uint(y);
    asm("prmt.b32 %0,%1,%2,0x7632;" : "=r"(hi) : "r"(ax), "r"(ay));
    float rx = x - __uint_as_float(ax & 0xffff0000u);
    float ry = y - __uint_as_float(ay & 0xffff0000u);
    asm("cvt.rn.bf16x2.f32 %0,%1,%2;" : "=r"(lo) : "f"(ry), "f"(rx));
}
// f16 split: hi = rn f16, lo = rn f16 of residual
__device__ __forceinline__ void split2_f16(float x, float y, u32& hi, u32& lo) {
    hi = f16pair(x, y);
    float hx, hy; h2unpack(hi, hx, hy);
    lo = f16pair(x - hx, y - hy);
}

// ---------------------------------------------------------------------------
// pre-split fp32 -> bf16 hi/lo; blockIdx.y selects one of up to 4 tensors
// ---------------------------------------------------------------------------
__global__ void split_bf16_multi(
    const float4* __restrict__ a0, const float4* __restrict__ a1,
    const float4* __restrict__ a2, const float4* __restrict__ a3,
    uint4* __restrict__ hi, uint4* __restrict__ lo, int n8)
{
    int g = blockIdx.y;
    const float4* in = (g == 0) ? a0 : (g == 1) ? a1 : (g == 2) ? a2 : a3;
    uint4* hp = hi + (size_t)g * n8;
    uint4* lp = lo + (size_t)g * n8;
    int idx = blockIdx.x * blockDim.x + threadIdx.x;
    int stride = gridDim.x * blockDim.x;
    for (int i = idx; i < n8; i += stride) {
        float4 a = __ldg(in + 2 * i), b = __ldg(in + 2 * i + 1);
        uint4 h, l;
        split2_bf16(a.x, a.y, h.x, l.x);
        split2_bf16(a.z, a.w, h.y, l.y);
        split2_bf16(b.x, b.y, h.z, l.z);
        split2_bf16(b.z, b.w, h.w, l.w);
        hp[i] = h; lp[i] = l;
    }
}

// ---------------------------------------------------------------------------
// Mask content check
// ---------------------------------------------------------------------------
__global__ void mask_check(const float* __restrict__ mask,
                           const unsigned char* __restrict__ kpm)
{
    int idx = blockIdx.x * blockDim.x + threadIdx.x;
    int stride = gridDim.x * blockDim.x;
    int any_m = 0;
    const float4* m4 = (const float4*)mask;
    for (int i = idx; i < (TT * SS) / 4; i += stride) {
        float4 v = __ldg(m4 + i);
        any_m |= (v.x != 0.f) | (v.y != 0.f) | (v.z != 0.f) | (v.w != 0.f);
    }
    int any_k = 0;
    const uint4* k4 = (const uint4*)kpm;
    for (int i = idx; i < (BB * SS) / 16; i += stride) {
        uint4 v = __ldg(k4 + i);
        any_k |= ((v.x | v.y | v.z | v.w) != 0u);
    }
    if (__any_sync(0xffffffffu, any_m) && (threadIdx.x & 31) == 0) atomicOr(&g_flags, 1);
    if (__any_sync(0xffffffffu, any_k) && (threadIdx.x & 31) == 0) atomicOr(&g_flags, 2);
}

// ---------------------------------------------------------------------------
// 3-stage cp.async bf16x3 GEMM, K-chunks of 16, SMALL CTAs (128 thr, 64x128
// tile, 4 CTAs/SM = 4 independent barrier domains).
// MODE 1: fused QKV (gi = blockIdx.x>>3); MODE 0: out-proj -> fp32.
// smem/stage: Ahi[64x48B] Alo Bhi[128x48B] Blo = 18432 B; 3 stages = 55296.
// ---------------------------------------------------------------------------
#define CH4 16
#define GST4 48
#define AT4 (64 * GST4)            // 3072
#define BT4 (128 * GST4)           // 6144
#define STG4 (2 * AT4 + 2 * BT4)   // 18432
#define GEMM4_SMEM (3 * STG4)      // 55296
// stage offsets: Ahi 0, Alo 3072, Bhi 6144, Blo 12288

template <int MODE>
__global__ __launch_bounds__(128, 4) void tc_gemm4(
    const u16* __restrict__ Ah_, const u16* __restrict__ Al_,
    const u16* __restrict__ Wh_, const u16* __restrict__ Wl_,
    const float* __restrict__ bq, const float* __restrict__ bk,
    const float* __restrict__ bv,
    void* __restrict__ oa, void* __restrict__ ob)
{
    extern __shared__ __align__(128) char dsm[];
    const u32 sb = smem_u32(dsm);
    const int tid = threadIdx.x;
    const int lane = tid & 31;
    const int wid = tid >> 5;          // 0..3
    const int wm = wid & 1;            // 2 warps along m (32 rows each)
    const int wn = wid >> 1;           // 2 warps along n (64 cols each)
    const int K = CC;
    const size_t XNs = (size_t)MT * CC;
    const size_t WNs = (size_t)CC * CC;

    int gi = 0, bnx = blockIdx.x;
    const float* bias = bq;
    float scale = 1.f;
    if (MODE == 1) {
        gi = blockIdx.x >> 3;
        bnx = blockIdx.x & 7;
        bias = (gi == 0) ? bq : (gi == 1) ? bk : bv;
        if (gi == 0) scale = SCALE_F;
    }
    const int bm = blockIdx.y * 64, bn = bnx * 128;

    const u16* Asrc[2] = { Ah_ + (size_t)gi * XNs + (size_t)bm * K,
                           Al_ + (size_t)gi * XNs + (size_t)bm * K };
    const u16* Bsrc[2] = { Wh_ + (size_t)gi * WNs + (size_t)bn * K,
                           Wl_ + (size_t)gi * WNs + (size_t)bn * K };

    const u32 aOff = (u32)((wm * 32 + (lane & 15)) * GST4 + (lane >> 4) * 16);
    const u32 bRow = (u32)(((lane >> 4) << 3) + (lane & 7));
    const u32 bOff = (u32)((wn * 64 + bRow) * GST4 + ((lane >> 3) & 1) * 16);

    float acc[2][8][4];
#pragma unroll
    for (int i = 0; i < 2; i++)
#pragma unroll
        for (int j = 0; j < 8; j++)
#pragma unroll
            for (int q = 0; q < 4; q++) acc[i][j][q] = 0.f;

    auto issue = [&](int c, int st) {
        u32 dbase = sb + st * STG4;
        // A: 256 16B slots (2 tiles x 64 rows x 2 segs), 2 per thread
#pragma unroll
        for (int i = 0; i < 2; i++) {
            int s = tid + i * 128;            // 0..255
            int t = (s >= 128) ? 1 : 0;
            int q = s & 127;
            int r = q >> 1, seg = q & 1;
            cpa16(dbase + t * AT4 + r * GST4 + seg * 16,
                  Asrc[t] + (size_t)r * K + c * CH4 + seg * 8);
        }
        // B: 512 slots (2 tiles x 128 rows x 2 segs), 4 per thread
#pragma unroll
        for (int i = 0; i < 4; i++) {
            int s = tid + i * 128;            // 0..511
            int t = (s >= 256) ? 1 : 0;
            int q = s & 255;
            int r = q >> 1, seg = q & 1;
            cpa16(dbase + 2 * AT4 + t * BT4 + r * GST4 + seg * 16,
                  Bsrc[t] + (size_t)r * K + c * CH4 + seg * 8);
        }
        cpa_commit();
    };

    issue(0, 0);
    issue(1, 1);
    const int nch = K / CH4;                      // 64
    for (int c = 0; c < nch; c++) {
        if (c + 1 < nch) cpa_wait<1>(); else cpa_wait<0>();
        __syncthreads();
        if (c + 2 < nch) issue(c + 2, (c + 2) % 3);

        const u32 base = sb + (c % 3) * STG4;
        const u32 aH = base + aOff, aL = aH + AT4;
        const u32 bH = base + 2 * AT4 + bOff, bL = bH + BT4;
        u32 ah[2][4], al[2][4];
#pragma unroll
        for (int mf = 0; mf < 2; mf++) {
            ldsm4(aH + mf * 768, ah[mf]);
            ldsm4(aL + mf * 768, al[mf]);
        }
#pragma unroll
        for (int pg = 0; pg < 2; pg++) {          // ng pairs {0,1},{2,3}
            u32 bh[2][4], bl[2][4];
#pragma unroll
            for (int g = 0; g < 2; g++) {
                ldsm4(bH + (pg * 2 + g) * 768, bh[g]);
                ldsm4(bL + (pg * 2 + g) * 768, bl[g]);
            }
#pragma unroll
            for (int g = 0; g < 2; g++)
#pragma unroll
                for (int half = 0; half < 2; half++)
#pragma unroll
                    for (int mf = 0; mf < 2; mf++)
                        mma_bf(acc[mf][(pg * 2 + g) * 2 + half], ah[mf], &bh[g][half * 2]);
#pragma unroll
            for (int g = 0; g < 2; g++)
#pragma unroll
                for (int half = 0; half < 2; half++)
#pragma unroll
                    for (int mf = 0; mf < 2; mf++)
                        mma_bf(acc[mf][(pg * 2 + g) * 2 + half], ah[mf], &bl[g][half * 2]);
#pragma unroll
            for (int g = 0; g < 2; g++)
#pragma unroll
                for (int half = 0; half < 2; half++)
#pragma unroll
                    for (int mf = 0; mf < 2; mf++)
                        mma_bf(acc[mf][(pg * 2 + g) * 2 + half], al[mf], &bh[g][half * 2]);
        }
        __syncthreads();
    }

#pragma unroll
    for (int mf = 0; mf < 2; mf++) {
#pragma unroll
        for (int nf = 0; nf < 8; nf++) {
            int m = bm + wm * 32 + mf * 16 + (lane >> 2);
            int n = bn + wn * 64 + nf * 8 + (lane & 3) * 2;
            float b0 = __ldg(bias + n), b1 = __ldg(bias + n + 1);
            if (MODE == 0) {
                float* out = (float*)oa;
                *(float2*)(out + (size_t)m * CC + n) =
                    make_float2(acc[mf][nf][0] + b0, acc[mf][nf][1] + b1);
                *(float2*)(out + (size_t)(m + 8) * CC + n) =
                    make_float2(acc[mf][nf][2] + b0, acc[mf][nf][3] + b1);
            } else {
                u32* oh = (u32*)((u16*)oa + (size_t)gi * XNs);
                u32* ol = (u32*)((u16*)ob + (size_t)gi * XNs);
                int h = n >> 6, d = n & (DD - 1);
                float v0 = (acc[mf][nf][0] + b0) * scale;
                float v1 = (acc[mf][nf][1] + b1) * scale;
                float v2 = (acc[mf][nf][2] + b0) * scale;
                float v3 = (acc[mf][nf][3] + b1) * scale;
                int b_ = m >> 11, t = m & (TT - 1);
                size_t idx0 = ((((size_t)b_ * HH + h) * TT + t) * DD + d) >> 1;
                u32 hi, lo;
                split2_f16(v0, v1, hi, lo);
                oh[idx0] = hi; ol[idx0] = lo;
                int m1 = m + 8;
                int b1_ = m1 >> 11, t1 = m1 & (TT - 1);
                size_t idx1 = ((((size_t)b1_ * HH + h) * TT + t1) * DD + d) >> 1;
                split2_f16(v2, v3, hi, lo);
                oh[idx1] = hi; ol[idx1] = lo;
            }
        }
    }
}

// ---------------------------------------------------------------------------
// Tensor-core flash attention (unchanged from R9, validated).
// ---------------------------------------------------------------------------
#define AST 144
#define AQLO 18432
#define AKV0 36864
#define AKVB 36864
#define ATTN_SMEM2 110592

__global__ __launch_bounds__(256, 2) void attn_tc2(
    const float* __restrict__ mask, const unsigned char* __restrict__ kpm,
    const u16* __restrict__ qh, const u16* __restrict__ ql,
    const u16* __restrict__ kh, const u16* __restrict__ kl,
    const u16* __restrict__ vh, const u16* __restrict__ vl,
    u16* __restrict__ ah_out, u16* __restrict__ al_out)
{
    extern __shared__ __align__(128) char smr[];
    const u32 sb = smem_u32(smr);

    const int tid = threadIdx.x;
    const int lane = tid & 31;
    const int w = tid >> 5;
    const int tblk = blockIdx.x * 128;
    const int h = blockIdx.y, b = blockIdx.z;
    const float NEGINF = __int_as_float(0xff800000);

    const int flags = g_flags;
    const bool mflag = (flags & 1) != 0;
    const bool kflag = (flags & 2) != 0;

    const size_t baseq = (((size_t)b * HH + h) * TT + tblk) * DD;
    const size_t basekv = ((size_t)b * HH + h) * (size_t)SS * DD;

#pragma unroll
    for (int t = 0; t < 2; t++) {
        const u16* src = (t ? ql : qh) + baseq;
#pragma unroll
        for (int i = 0; i < 4; i++) {
            int s = tid + i * 256;
            int r = s >> 3, j = s & 7;
            cpa16(sb + t * AQLO + r * AST + j * 16, src + (size_t)r * DD + j * 8);
        }
    }
    cpa_commit();

    auto issueKV = [&](int s0, int buf) {
        const u16* srcs[4] = { kh + basekv, kl + basekv, vh + basekv, vl + basekv };
        u32 dbase = sb + AKV0 + buf * AKVB;
#pragma unroll
        for (int t = 0; t < 4; t++) {
#pragma unroll
            for (int i = 0; i < 2; i++) {
                int s = tid + i * 256;
                int r = s >> 3, j = s & 7;
                cpa16(dbase + t * 9216 + r * AST + j * 16,
                      srcs[t] + (size_t)(s0 + r) * DD + j * 8);
            }
        }
        cpa_commit();
    };
    issueKV(0, 0);

    const u32 aQ = sb + (u32)((w * 16 + (lane & 15)) * AST + (lane >> 4) * 16);
    const u32 bKoff = (u32)((((lane >> 4) << 3) + (lane & 7)) * AST + ((lane >> 3) & 1) * 16);
    const u32 bVoff = (u32)((lane & 15) * AST + (lane >> 4) * 16);

    const int row0 = tblk + w * 16 + (lane >> 2);
    const float* mrow0 = mask + (size_t)row0 * SS;
    const float* mrow1 = mrow0 + 8 * (size_t)SS;

    float O[8][4];
#pragma unroll
    for (int i = 0; i < 8; i++)
#pragma unroll
        for (int j = 0; j < 4; j++) O[i][j] = 0.f;
    float l0 = 0.f, l1 = 0.f, m0 = NEGINF, m1 = NEGINF;

    int buf = 0;
    for (int c = 0; c < SS / 64; c++) {
        const int s0 = c * 64;
        cpa_wait<0>();
        __syncthreads();
        if (c + 1 < SS / 64) issueKV(s0 + 64, buf ^ 1);

        const u32 kvb = sb + AKV0 + buf * AKVB;
        const u32 bK = kvb + bKoff;
        const u32 bV = kvb + 18432 + bVoff;

        float sacc[8][4];
#pragma unroll
        for (int i = 0; i < 8; i++)
#pragma unroll
            for (int j = 0; j < 4; j++) sacc[i][j] = 0.f;
#pragma unroll
        for (int ks = 0; ks < 4; ks++) {
            u32 ahf[4], alf[4];
            ldsm4(aQ + ks * 32, ahf);
            ldsm4(aQ + AQLO + ks * 32, alf);
#pragma unroll
            for (int pg = 0; pg < 2; pg++) {
                u32 bh[2][4], bl[2][4];
#pragma unroll
                for (int g = 0; g < 2; g++) {
                    ldsm4(bK + (pg * 2 + g) * 2304 + ks * 32, bh[g]);
                    ldsm4(bK + 9216 + (pg * 2 + g) * 2304 + ks * 32, bl[g]);
                }
#pragma unroll
                for (int g = 0; g < 2; g++)
#pragma unroll
                    for (int half = 0; half < 2; half++)
                        mma_f16(sacc[(pg * 2 + g) * 2 + half], ahf, &bh[g][half * 2]);
#pragma unroll
                for (int g = 0; g < 2; g++)
#pragma unroll
                    for (int half = 0; half < 2; half++)
                        mma_f16(sacc[(pg * 2 + g) * 2 + half], ahf, &bl[g][half * 2]);
#pragma unroll
                for (int g = 0; g < 2; g++)
#pragma unroll
                    for (int half = 0; half < 2; half++)
                        mma_f16(sacc[(pg * 2 + g) * 2 + half], alf, &bh[g][half * 2]);
            }
        }

        if (kflag) {
#pragma unroll
            for (int nf = 0; nf < 8; nf++) {
                int col = s0 + nf * 8 + (lane & 3) * 2;
                float k0 = kpm[(size_t)b * SS + col] ? NEGINF : 0.f;
                float k1 = kpm[(size_t)b * SS + col + 1] ? NEGINF : 0.f;
                sacc[nf][0] += k0; sacc[nf][1] += k1;
                sacc[nf][2] += k0; sacc[nf][3] += k1;
            }
        }
        if (mflag) {
#pragma unroll
            for (int nf = 0; nf < 8; nf++) {
                int col = s0 + nf * 8 + (lane & 3) * 2;
                float2 mv0 = __ldg((const float2*)(mrow0 + col));
                float2 mv1 = __ldg((const float2*)(mrow1 + col));
                sacc[nf][0] += mv0.x; sacc[nf][1] += mv0.y;
                sacc[nf][2] += mv1.x; sacc[nf][3] += mv1.y;
            }
        }

        float cm0 = NEGINF, cm1 = NEGINF;
#pragma unroll
        for (int nf = 0; nf < 8; nf++) {
            cm0 = fmaxf(cm0, fmaxf(sacc[nf][0], sacc[nf][1]));
            cm1 = fmaxf(cm1, fmaxf(sacc[nf][2], sacc[nf][3]));
        }
        cm0 = fmaxf(cm0, __shfl_xor_sync(0xffffffffu, cm0, 1));
        cm0 = fmaxf(cm0, __shfl_xor_sync(0xffffffffu, cm0, 2));
        cm1 = fmaxf(cm1, __shfl_xor_sync(0xffffffffu, cm1, 1));
        cm1 = fmaxf(cm1, __shfl_xor_sync(0xffffffffu, cm1, 2));

        float mn0 = fmaxf(m0, cm0), mn1 = fmaxf(m1, cm1);
        float c0 = __expf(m0 - mn0), c1 = __expf(m1 - mn1);
        m0 = mn0; m1 = mn1;
        l0 *= c0; l1 *= c1;
#pragma unroll
        for (int nf = 0; nf < 8; nf++) {
            O[nf][0] *= c0; O[nf][1] *= c0;
            O[nf][2] *= c1; O[nf][3] *= c1;
        }

        u32 phi[8][2];
        float rs0 = 0.f, rs1 = 0.f;
#pragma unroll
        for (int nf = 0; nf < 8; nf++) {
            float p0 = __expf(sacc[nf][0] - mn0);
            float p1 = __expf(sacc[nf][1] - mn0);
            float p2 = __expf(sacc[nf][2] - mn1);
            float p3 = __expf(sacc[nf][3] - mn1);
            rs0 += p0 + p1; rs1 += p2 + p3;
            phi[nf][0] = f16pair(p0, p1);
            phi[nf][1] = f16pair(p2, p3);
        }
        rs0 += __shfl_xor_sync(0xffffffffu, rs0, 1);
        rs0 += __shfl_xor_sync(0xffffffffu, rs0, 2);
        rs1 += __shfl_xor_sync(0xffffffffu, rs1, 1);
        rs1 += __shfl_xor_sync(0xffffffffu, rs1, 2);
        l0 += rs0; l1 += rs1;

#pragma unroll
        for (int ks = 0; ks < 4; ks++) {
            u32 ap[4] = {phi[2 * ks][0], phi[2 * ks][1],
                         phi[2 * ks + 1][0], phi[2 * ks + 1][1]};
#pragma unroll
            for (int pd = 0; pd < 2; pd++) {
                u32 bh[2][4], bl[2][4];
#pragma unroll
                for (int g = 0; g < 2; g++) {
                    ldsm4t(bV + ks * 2304 + (pd * 2 + g) * 32, bh[g]);
                    ldsm4t(bV + 9216 + ks * 2304 + (pd * 2 + g) * 32, bl[g]);
                }
#pragma unroll
                for (int g = 0; g < 2; g++)
#pragma unroll
                    for (int half = 0; half < 2; half++)
                        mma_f16(O[(pd * 2 + g) * 2 + half], ap, &bh[g][half * 2]);
#pragma unroll
                for (int g = 0; g < 2; g++)
#pragma unroll
                    for (int half = 0; half < 2; half++)
                        mma_f16(O[(pd * 2 + g) * 2 + half], ap, &bl[g][half * 2]);
            }
        }
        buf ^= 1;
    }

    float i0 = __fdividef(1.f, l0), i1 = __fdividef(1.f, l1);
    size_t base0 = ((size_t)b * TT + row0) * CC + h * DD + (lane & 3) * 2;
    size_t base1 = base0 + 8 * (size_t)CC;
    u32* oh = (u32*)ah_out;
    u32* ol = (u32*)al_out;
#pragma unroll
    for (int nf = 0; nf < 8; nf++) {
        u32 hi, lo;
        split2_bf16(O[nf][0] * i0, O[nf][1] * i0, hi, lo);
        oh[(base0 + nf * 8) >> 1] = hi; ol[(base0 + nf * 8) >> 1] = lo;
        split2_bf16(O[nf][2] * i1, O[nf][3] * i1, hi, lo);
        oh[(base1 + nf * 8) >> 1] = hi; ol[(base1 + nf * 8) >> 1] = lo;
    }
}

// ---------------------------------------------------------------------------
// Launch
// ---------------------------------------------------------------------------
extern "C" void kernel_launch(void* const* d_in, const int* in_sizes, int n_in,
                              void* d_out, int out_size)
{
    (void)in_sizes; (void)n_in; (void)out_size;
    const float* query = (const float*)d_in[0];
    const float* key   = (const float*)d_in[1];
    const float* value = (const float*)d_in[2];
    const float* mask  = (const float*)d_in[3];
    const unsigned char* kpm = (const unsigned char*)d_in[4];
    const float* Wq = (const float*)d_in[5];
    const float* bq = (const float*)d_in[6];
    const float* Wk = (const float*)d_in[7];
    const float* bk = (const float*)d_in[8];
    const float* Wv = (const float*)d_in[9];
    const float* bv = (const float*)d_in[10];
    const float* Wout = (const float*)d_in[11];
    const float* bout = (const float*)d_in[12];
    float* out = (float*)d_out;

    u16 *xh, *xl, *wh, *wl, *ph, *pl, *ah, *al;
    int* fp;
    cudaGetSymbolAddress((void**)&xh, g_xh);
    cudaGetSymbolAddress((void**)&xl, g_xl);
    cudaGetSymbolAddress((void**)&wh, g_wh);
    cudaGetSymbolAddress((void**)&wl, g_wl);
    cudaGetSymbolAddress((void**)&ph, g_ph);
    cudaGetSymbolAddress((void**)&pl, g_pl);
    cudaGetSymbolAddress((void**)&ah, g_ah);
    cudaGetSymbolAddress((void**)&al, g_al);
    cudaGetSymbolAddress((void**)&fp, g_flags);

    const size_t XN = (size_t)MT * CC;
    const size_t WN = (size_t)CC * CC;
    const size_t PN = (size_t)BB * HH * TT * DD;

    cudaFuncSetAttribute(tc_gemm4<0>, cudaFuncAttributeMaxDynamicSharedMemorySize, GEMM4_SMEM);
    cudaFuncSetAttribute(tc_gemm4<1>, cudaFuncAttributeMaxDynamicSharedMemorySize, GEMM4_SMEM);
    cudaFuncSetAttribute(attn_tc2, cudaFuncAttributeMaxDynamicSharedMemorySize, ATTN_SMEM2);

    cudaMemsetAsync(fp, 0, sizeof(int));
    mask_check<<<1024, 256>>>(mask, kpm);

    split_bf16_multi<<<dim3(512, 3), 256>>>(
        (const float4*)query, (const float4*)key, (const float4*)value,
        (const float4*)query, (uint4*)xh, (uint4*)xl, (int)(XN / 8));
    split_bf16_multi<<<dim3(256, 4), 256>>>(
        (const float4*)Wq, (const float4*)Wk, (const float4*)Wv,
        (const float4*)Wout, (uint4*)wh, (uint4*)wl, (int)(WN / 8));

    // fused QKV projections: grid (3*8 n-tiles, 128 m-tiles of 64 rows)
    tc_gemm4<1><<<dim3(24, MT / 64), 128, GEMM4_SMEM>>>(
        xh, xl, wh, wl, bq, bk, bv, ph, pl);

    attn_tc2<<<dim3(TT / 128, HH, BB), 256, ATTN_SMEM2>>>(
        mask, kpm,
        ph + 0 * PN, pl + 0 * PN,
        ph + 1 * PN, pl + 1 * PN,
        ph + 2 * PN, pl + 2 * PN,
        ah, al);

    // output projection
    tc_gemm4<0><<<dim3(8, MT / 64), 128, GEMM4_SMEM>>>(
        ah, al, wh + 3 * WN, wl + 3 * WN, bout, bout, bout, out, nullptr);
}

// round 12
// speedup vs baseline: 1.9430x; 1.9430x over previous
#include <cuda_runtime.h>
#include <cuda_fp16.h>
#include <cstdint>

#define BB 4
#define TT 2048
#define SS 2048
#define CC 1024
#define HH 16
#define DD 64
#define SCALE_F 0.125f
#define MT (BB * TT)

typedef unsigned long long u64;
typedef unsigned int u32;
typedef unsigned short u16;

// ---------------------------------------------------------------------------
// Scratch (allocation-free rule: __device__ globals)
// ---------------------------------------------------------------------------
__device__ u16 g_ph[3][BB * HH * TT * DD]; // projected q,k,v f16 hi (B,H,T,D)
__device__ u16 g_pl[3][BB * HH * TT * DD]; // f16 lo
__device__ u16 g_ao[MT * CC];              // attn out f16 (B,T,C)
__device__ int g_flags;                    // bit0: mask nonzero, bit1: kpm any

// ---------------------------------------------------------------------------
// helpers
// ---------------------------------------------------------------------------
__device__ __forceinline__ u32 smem_u32(const void* p) {
    u32 a;
    asm("{ .reg .u64 t; cvta.to.shared.u64 t, %1; cvt.u32.u64 %0, t; }" : "=r"(a) : "l"(p));
    return a;
}
__device__ __forceinline__ void ldsm4(u32 addr, u32* r) {
    asm volatile("ldmatrix.sync.aligned.m8n8.x4.shared.b16 {%0,%1,%2,%3},[%4];"
                 : "=r"(r[0]), "=r"(r[1]), "=r"(r[2]), "=r"(r[3]) : "r"(addr));
}
__device__ __forceinline__ void ldsm4t(u32 addr, u32* r) {
    asm volatile("ldmatrix.sync.aligned.m8n8.x4.trans.shared.b16 {%0,%1,%2,%3},[%4];"
                 : "=r"(r[0]), "=r"(r[1]), "=r"(r[2]), "=r"(r[3]) : "r"(addr));
}
__device__ __forceinline__ void mma_f16(float* c, const u32* a, const u32* b) {
    asm volatile(
        "mma.sync.aligned.m16n8k16.row.col.f32.f16.f16.f32 "
        "{%0,%1,%2,%3},{%4,%5,%6,%7},{%8,%9},{%0,%1,%2,%3};"
        : "+f"(c[0]), "+f"(c[1]), "+f"(c[2]), "+f"(c[3])
        : "r"(a[0]), "r"(a[1]), "r"(a[2]), "r"(a[3]), "r"(b[0]), "r"(b[1]));
}
__device__ __forceinline__ u32 f16pair(float lo, float hi) {
    u32 r; asm("cvt.rn.f16x2.f32 %0,%1,%2;" : "=r"(r) : "f"(hi), "f"(lo)); return r;
}
__device__ __forceinline__ void h2unpack(u32 v, float& lo, float& hi) {
    asm("{.reg .b16 l,h; mov.b32 {l,h}, %2; cvt.f32.f16 %0, l; cvt.f32.f16 %1, h;}"
        : "=f"(lo), "=f"(hi) : "r"(v));
}
__device__ __forceinline__ void cpa16(u32 dst, const void* src) {
    asm volatile("cp.async.cg.shared.global [%0], [%1], 16;" :: "r"(dst), "l"(src));
}
__device__ __forceinline__ void cpa_commit() {
    asm volatile("cp.async.commit_group;" ::: "memory");
}
template <int N>
__device__ __forceinline__ void cpa_wait() {
    asm volatile("cp.async.wait_group %0;" :: "n"(N) : "memory");
}
// f16 split: hi = rn f16, lo = rn f16 of residual
__device__ __forceinline__ void split2_f16(float x, float y, u32& hi, u32& lo) {
    hi = f16pair(x, y);
    float hx, hy; h2unpack(hi, hx, hy);
    lo = f16pair(x - hx, y - hy);
}

// ---------------------------------------------------------------------------
// Mask content check
// ---------------------------------------------------------------------------
__global__ void mask_check(const float* __restrict__ mask,
                           const unsigned char* __restrict__ kpm)
{
    int idx = blockIdx.x * blockDim.x + threadIdx.x;
    int stride = gridDim.x * blockDim.x;
    int any_m = 0;
    const float4* m4 = (const float4*)mask;
    for (int i = idx; i < (TT * SS) / 4; i += stride) {
        float4 v = __ldg(m4 + i);
        any_m |= (v.x != 0.f) | (v.y != 0.f) | (v.z != 0.f) | (v.w != 0.f);
    }
    int any_k = 0;
    const uint4* k4 = (const uint4*)kpm;
    for (int i = idx; i < (BB * SS) / 16; i += stride) {
        uint4 v = __ldg(k4 + i);
        any_k |= ((v.x | v.y | v.z | v.w) != 0u);
    }
    if (__any_sync(0xffffffffu, any_m) && (threadIdx.x & 31) == 0) atomicOr(&g_flags, 1);
    if (__any_sync(0xffffffffu, any_k) && (threadIdx.x & 31) == 0) atomicOr(&g_flags, 2);
}

// ---------------------------------------------------------------------------
// f16x2 GEMM (R6-best skeleton): out = A @ W^T + bias.
// A single f16 (rn), W split f16 hi+lo: 2 MMAs per fragment (dropped a_lo·b
// term ~2^-12). 128x128 tile, 256 thr, 2 CTA/SM, K-chunks of 64, convert
// in-kernel.
// MODE 1: A fp32 input; epilogue scatters f16 hi/lo split to (B,H,T,D) * scale.
// MODE 0: A f16 (u16) input; epilogue writes fp32 row-major + bias.
// smem: Af[128][72]f16 @0, Bhi @18432, Blo @36864 (row stride 144B).
// ---------------------------------------------------------------------------
#define GST5 144
#define GT5 (128 * GST5)          // 18432
#define GEMM5_SMEM (3 * GT5)      // 55296

template <int MODE>
__global__ __launch_bounds__(256, 2) void tc_gemm5(
    const void* __restrict__ A_, const float* __restrict__ W,
    const float* __restrict__ bias, float scale,
    void* __restrict__ oa, void* __restrict__ ob)
{
    extern __shared__ __align__(128) char dsm[];
    char* Af = dsm;
    char* Bhi = dsm + GT5;
    char* Blo = dsm + 2 * GT5;
    const u32 sb = smem_u32(dsm);

    const int tid = threadIdx.x;
    const int lane = tid & 31;
    const int wid = tid >> 5;
    const int wm = wid & 3;
    const int wn = wid >> 2;
    const int bm = blockIdx.y * 128, bn = blockIdx.x * 128;
    const int K = CC;

    const u32 aOff = (u32)((wm * 32 + (lane & 15)) * GST5 + (lane >> 4) * 16);
    const u32 bRow = (u32)(((lane >> 4) << 3) + (lane & 7));
    const u32 bOff = (u32)((wn * 64 + bRow) * GST5 + ((lane >> 3) & 1) * 16);

    float acc[2][8][4];
#pragma unroll
    for (int i = 0; i < 2; i++)
#pragma unroll
        for (int j = 0; j < 8; j++)
#pragma unroll
            for (int q = 0; q < 4; q++) acc[i][j][q] = 0.f;

    const float* Wp = W + (size_t)bn * K;

    for (int k0 = 0; k0 < K; k0 += 64) {
#pragma unroll
        for (int i = 0; i < 8; i++) {
            int f = tid + i * 256;                 // 0..2047 slots (4 elems each)
            int r = f >> 4, kq = (f & 15) << 2;
            u32 soff = (u32)(r * GST5 + kq * 2);
            if (MODE == 1) {
                const float* Ap = (const float*)A_ + (size_t)bm * K;
                float4 a = __ldg((const float4*)(Ap + (size_t)r * K + k0 + kq));
                u32 p01 = f16pair(a.x, a.y);
                u32 p23 = f16pair(a.z, a.w);
                *(uint2*)(Af + soff) = make_uint2(p01, p23);
            } else {
                const u16* Ap = (const u16*)A_ + (size_t)bm * K;
                uint2 v = __ldg((const uint2*)(Ap + (size_t)r * K + k0 + kq));
                *(uint2*)(Af + soff) = v;
            }
            float4 w = __ldg((const float4*)(Wp + (size_t)r * K + k0 + kq));
            u32 h01, l01, h23, l23;
            split2_f16(w.x, w.y, h01, l01);
            split2_f16(w.z, w.w, h23, l23);
            *(uint2*)(Bhi + soff) = make_uint2(h01, h23);
            *(uint2*)(Blo + soff) = make_uint2(l01, l23);
        }
        __syncthreads();

        const u32 aA = sb + aOff;
        const u32 bHA = sb + GT5 + bOff;
        const u32 bLA = sb + 2 * GT5 + bOff;
#pragma unroll
        for (int ks = 0; ks < 4; ks++) {
            u32 ah[2][4];
#pragma unroll
            for (int mf = 0; mf < 2; mf++)
                ldsm4(aA + mf * 2304 + ks * 32, ah[mf]);
#pragma unroll
            for (int ng = 0; ng < 4; ng++) {
                u32 bh[4], bl[4];
                ldsm4(bHA + ng * 2304 + ks * 32, bh);
                ldsm4(bLA + ng * 2304 + ks * 32, bl);
#pragma unroll
                for (int half = 0; half < 2; half++) {
                    int nf = ng * 2 + half;
#pragma unroll
                    for (int mf = 0; mf < 2; mf++) {
                        mma_f16(acc[mf][nf], ah[mf], &bh[half * 2]);
                        mma_f16(acc[mf][nf], ah[mf], &bl[half * 2]);
                    }
                }
            }
        }
        __syncthreads();
    }

#pragma unroll
    for (int mf = 0; mf < 2; mf++) {
#pragma unroll
        for (int nf = 0; nf < 8; nf++) {
            int m = bm + wm * 32 + mf * 16 + (lane >> 2);
            int n = bn + wn * 64 + nf * 8 + (lane & 3) * 2;
            float b0 = __ldg(bias + n), b1 = __ldg(bias + n + 1);
            if (MODE == 0) {
                float* out = (float*)oa;
                *(float2*)(out + (size_t)m * CC + n) =
                    make_float2(acc[mf][nf][0] + b0, acc[mf][nf][1] + b1);
                *(float2*)(out + (size_t)(m + 8) * CC + n) =
                    make_float2(acc[mf][nf][2] + b0, acc[mf][nf][3] + b1);
            } else {
                u32* oh = (u32*)oa;
                u32* ol = (u32*)ob;
                int h = n >> 6, d = n & (DD - 1);
                float v0 = (acc[mf][nf][0] + b0) * scale;
                float v1 = (acc[mf][nf][1] + b1) * scale;
                float v2 = (acc[mf][nf][2] + b0) * scale;
                float v3 = (acc[mf][nf][3] + b1) * scale;
                int b_ = m >> 11, t = m & (TT - 1);
                size_t idx0 = ((((size_t)b_ * HH + h) * TT + t) * DD + d) >> 1;
                u32 hi, lo;
                split2_f16(v0, v1, hi, lo);
                oh[idx0] = hi; ol[idx0] = lo;
                int m1 = m + 8;
                int b1_ = m1 >> 11, t1 = m1 & (TT - 1);
                size_t idx1 = ((((size_t)b1_ * HH + h) * TT + t1) * DD + d) >> 1;
                split2_f16(v2, v3, hi, lo);
                oh[idx1] = hi; ol[idx1] = lo;
            }
        }
    }
}

// ---------------------------------------------------------------------------
// Tensor-core flash attention (R9-validated math; epilogue -> f16 single).
// ---------------------------------------------------------------------------
#define AST 144
#define AQLO 18432
#define AKV0 36864
#define AKVB 36864
#define ATTN_SMEM2 110592

__global__ __launch_bounds__(256, 2) void attn_tc2(
    const float* __restrict__ mask, const unsigned char* __restrict__ kpm,
    const u16* __restrict__ qh, const u16* __restrict__ ql,
    const u16* __restrict__ kh, const u16* __restrict__ kl,
    const u16* __restrict__ vh, const u16* __restrict__ vl,
    u16* __restrict__ ao_out)
{
    extern __shared__ __align__(128) char smr[];
    const u32 sb = smem_u32(smr);

    const int tid = threadIdx.x;
    const int lane = tid & 31;
    const int w = tid >> 5;
    const int tblk = blockIdx.x * 128;
    const int h = blockIdx.y, b = blockIdx.z;
    const float NEGINF = __int_as_float(0xff800000);

    const int flags = g_flags;
    const bool mflag = (flags & 1) != 0;
    const bool kflag = (flags & 2) != 0;

    const size_t baseq = (((size_t)b * HH + h) * TT + tblk) * DD;
    const size_t basekv = ((size_t)b * HH + h) * (size_t)SS * DD;

#pragma unroll
    for (int t = 0; t < 2; t++) {
        const u16* src = (t ? ql : qh) + baseq;
#pragma unroll
        for (int i = 0; i < 4; i++) {
            int s = tid + i * 256;
            int r = s >> 3, j = s & 7;
            cpa16(sb + t * AQLO + r * AST + j * 16, src + (size_t)r * DD + j * 8);
        }
    }
    cpa_commit();

    auto issueKV = [&](int s0, int buf) {
        const u16* srcs[4] = { kh + basekv, kl + basekv, vh + basekv, vl + basekv };
        u32 dbase = sb + AKV0 + buf * AKVB;
#pragma unroll
        for (int t = 0; t < 4; t++) {
#pragma unroll
            for (int i = 0; i < 2; i++) {
                int s = tid + i * 256;
                int r = s >> 3, j = s & 7;
                cpa16(dbase + t * 9216 + r * AST + j * 16,
                      srcs[t] + (size_t)(s0 + r) * DD + j * 8);
            }
        }
        cpa_commit();
    };
    issueKV(0, 0);

    const u32 aQ = sb + (u32)((w * 16 + (lane & 15)) * AST + (lane >> 4) * 16);
    const u32 bKoff = (u32)((((lane >> 4) << 3) + (lane & 7)) * AST + ((lane >> 3) & 1) * 16);
    const u32 bVoff = (u32)((lane & 15) * AST + (lane >> 4) * 16);

    const int row0 = tblk + w * 16 + (lane >> 2);
    const float* mrow0 = mask + (size_t)row0 * SS;
    const float* mrow1 = mrow0 + 8 * (size_t)SS;

    float O[8][4];
#pragma unroll
    for (int i = 0; i < 8; i++)
#pragma unroll
        for (int j = 0; j < 4; j++) O[i][j] = 0.f;
    float l0 = 0.f, l1 = 0.f, m0 = NEGINF, m1 = NEGINF;

    int buf = 0;
    for (int c = 0; c < SS / 64; c++) {
        const int s0 = c * 64;
        cpa_wait<0>();
        __syncthreads();
        if (c + 1 < SS / 64) issueKV(s0 + 64, buf ^ 1);

        const u32 kvb = sb + AKV0 + buf * AKVB;
        const u32 bK = kvb + bKoff;
        const u32 bV = kvb + 18432 + bVoff;

        float sacc[8][4];
#pragma unroll
        for (int i = 0; i < 8; i++)
#pragma unroll
            for (int j = 0; j < 4; j++) sacc[i][j] = 0.f;
#pragma unroll
        for (int ks = 0; ks < 4; ks++) {
            u32 ahf[4], alf[4];
            ldsm4(aQ + ks * 32, ahf);
            ldsm4(aQ + AQLO + ks * 32, alf);
#pragma unroll
            for (int pg = 0; pg < 2; pg++) {
                u32 bh[2][4], bl[2][4];
#pragma unroll
                for (int g = 0; g < 2; g++) {
                    ldsm4(bK + (pg * 2 + g) * 2304 + ks * 32, bh[g]);
                    ldsm4(bK + 9216 + (pg * 2 + g) * 2304 + ks * 32, bl[g]);
                }
#pragma unroll
                for (int g = 0; g < 2; g++)
#pragma unroll
                    for (int half = 0; half < 2; half++)
                        mma_f16(sacc[(pg * 2 + g) * 2 + half], ahf, &bh[g][half * 2]);
#pragma unroll
                for (int g = 0; g < 2; g++)
#pragma unroll
                    for (int half = 0; half < 2; half++)
                        mma_f16(sacc[(pg * 2 + g) * 2 + half], ahf, &bl[g][half * 2]);
#pragma unroll
                for (int g = 0; g < 2; g++)
#pragma unroll
                    for (int half = 0; half < 2; half++)
                        mma_f16(sacc[(pg * 2 + g) * 2 + half], alf, &bh[g][half * 2]);
            }
        }

        if (kflag) {
#pragma unroll
            for (int nf = 0; nf < 8; nf++) {
                int col = s0 + nf * 8 + (lane & 3) * 2;
                float k0 = kpm[(size_t)b * SS + col] ? NEGINF : 0.f;
                float k1 = kpm[(size_t)b * SS + col + 1] ? NEGINF : 0.f;
                sacc[nf][0] += k0; sacc[nf][1] += k1;
                sacc[nf][2] += k0; sacc[nf][3] += k1;
            }
        }
        if (mflag) {
#pragma unroll
            for (int nf = 0; nf < 8; nf++) {
                int col = s0 + nf * 8 + (lane & 3) * 2;
                float2 mv0 = __ldg((const float2*)(mrow0 + col));
                float2 mv1 = __ldg((const float2*)(mrow1 + col));
                sacc[nf][0] += mv0.x; sacc[nf][1] += mv0.y;
                sacc[nf][2] += mv1.x; sacc[nf][3] += mv1.y;
            }
        }

        float cm0 = NEGINF, cm1 = NEGINF;
#pragma unroll
        for (int nf = 0; nf < 8; nf++) {
            cm0 = fmaxf(cm0, fmaxf(sacc[nf][0], sacc[nf][1]));
            cm1 = fmaxf(cm1, fmaxf(sacc[nf][2], sacc[nf][3]));
        }
        cm0 = fmaxf(cm0, __shfl_xor_sync(0xffffffffu, cm0, 1));
        cm0 = fmaxf(cm0, __shfl_xor_sync(0xffffffffu, cm0, 2));
        cm1 = fmaxf(cm1, __shfl_xor_sync(0xffffffffu, cm1, 1));
        cm1 = fmaxf(cm1, __shfl_xor_sync(0xffffffffu, cm1, 2));

        float mn0 = fmaxf(m0, cm0), mn1 = fmaxf(m1, cm1);
        float c0 = __expf(m0 - mn0), c1 = __expf(m1 - mn1);
        m0 = mn0; m1 = mn1;
        l0 *= c0; l1 *= c1;
#pragma unroll
        for (int nf = 0; nf < 8; nf++) {
            O[nf][0] *= c0; O[nf][1] *= c0;
            O[nf][2] *= c1; O[nf][3] *= c1;
        }

        u32 phi[8][2];
        float rs0 = 0.f, rs1 = 0.f;
#pragma unroll
        for (int nf = 0; nf < 8; nf++) {
            float p0 = __expf(sacc[nf][0] - mn0);
            float p1 = __expf(sacc[nf][1] - mn0);
            float p2 = __expf(sacc[nf][2] - mn1);
            float p3 = __expf(sacc[nf][3] - mn1);
            rs0 += p0 + p1; rs1 += p2 + p3;
            phi[nf][0] = f16pair(p0, p1);
            phi[nf][1] = f16pair(p2, p3);
        }
        rs0 += __shfl_xor_sync(0xffffffffu, rs0, 1);
        rs0 += __shfl_xor_sync(0xffffffffu, rs0, 2);
        rs1 += __shfl_xor_sync(0xffffffffu, rs1, 1);
        rs1 += __shfl_xor_sync(0xffffffffu, rs1, 2);
        l0 += rs0; l1 += rs1;

#pragma unroll
        for (int ks = 0; ks < 4; ks++) {
            u32 ap[4] = {phi[2 * ks][0], phi[2 * ks][1],
                         phi[2 * ks + 1][0], phi[2 * ks + 1][1]};
#pragma unroll
            for (int pd = 0; pd < 2; pd++) {
                u32 bh[2][4], bl[2][4];
#pragma unroll
                for (int g = 0; g < 2; g++) {
                    ldsm4t(bV + ks * 2304 + (pd * 2 + g) * 32, bh[g]);
                    ldsm4t(bV + 9216 + ks * 2304 + (pd * 2 + g) * 32, bl[g]);
                }
#pragma unroll
                for (int g = 0; g < 2; g++)
#pragma unroll
                    for (int half = 0; half < 2; half++)
                        mma_f16(O[(pd * 2 + g) * 2 + half], ap, &bh[g][half * 2]);
#pragma unroll
                for (int g = 0; g < 2; g++)
#pragma unroll
                    for (int half = 0; half < 2; half++)
                        mma_f16(O[(pd * 2 + g) * 2 + half], ap, &bl[g][half * 2]);
            }
        }
        buf ^= 1;
    }

    // epilogue: normalize, write f16 (rn) to (B,T,C)
    float i0 = __fdividef(1.f, l0), i1 = __fdividef(1.f, l1);
    size_t base0 = ((size_t)b * TT + row0) * CC + h * DD + (lane & 3) * 2;
    size_t base1 = base0 + 8 * (size_t)CC;
    u32* oa = (u32*)ao_out;
#pragma unroll
    for (int nf = 0; nf < 8; nf++) {
        oa[(base0 + nf * 8) >> 1] = f16pair(O[nf][0] * i0, O[nf][1] * i0);
        oa[(base1 + nf * 8) >> 1] = f16pair(O[nf][2] * i1, O[nf][3] * i1);
    }
}

// ---------------------------------------------------------------------------
// Launch
// ---------------------------------------------------------------------------
extern "C" void kernel_launch(void* const* d_in, const int* in_sizes, int n_in,
                              void* d_out, int out_size)
{
    (void)in_sizes; (void)n_in; (void)out_size;
    const float* query = (const float*)d_in[0];
    const float* key   = (const float*)d_in[1];
    const float* value = (const float*)d_in[2];
    const float* mask  = (const float*)d_in[3];
    const unsigned char* kpm = (const unsigned char*)d_in[4];
    const float* Wq = (const float*)d_in[5];
    const float* bq = (const float*)d_in[6];
    const float* Wk = (const float*)d_in[7];
    const float* bk = (const float*)d_in[8];
    const float* Wv = (const float*)d_in[9];
    const float* bv = (const float*)d_in[10];
    const float* Wout = (const float*)d_in[11];
    const float* bout = (const float*)d_in[12];
    float* out = (float*)d_out;

    u16 *ph, *pl, *ao;
    int* fp;
    cudaGetSymbolAddress((void**)&ph, g_ph);
    cudaGetSymbolAddress((void**)&pl, g_pl);
    cudaGetSymbolAddress((void**)&ao, g_ao);
    cudaGetSymbolAddress((void**)&fp, g_flags);

    const size_t PN = (size_t)BB * HH * TT * DD;

    cudaFuncSetAttribute(tc_gemm5<0>, cudaFuncAttributeMaxDynamicSharedMemorySize, GEMM5_SMEM);
    cudaFuncSetAttribute(tc_gemm5<1>, cudaFuncAttributeMaxDynamicSharedMemorySize, GEMM5_SMEM);
    cudaFuncSetAttribute(attn_tc2, cudaFuncAttributeMaxDynamicSharedMemorySize, ATTN_SMEM2);

    cudaMemsetAsync(fp, 0, sizeof(int));
    mask_check<<<1024, 256>>>(mask, kpm);

    dim3 ggrid(CC / 128, MT / 128);   // (8, 64)
    tc_gemm5<1><<<ggrid, 256, GEMM5_SMEM>>>(query, Wq, bq, SCALE_F,
                                            ph + 0 * PN, pl + 0 * PN);
    tc_gemm5<1><<<ggrid, 256, GEMM5_SMEM>>>(key,   Wk, bk, 1.0f,
                                            ph + 1 * PN, pl + 1 * PN);
    tc_gemm5<1><<<ggrid, 256, GEMM5_SMEM>>>(value, Wv, bv, 1.0f,
                                            ph + 2 * PN, pl + 2 * PN);

    attn_tc2<<<dim3(TT / 128, HH, BB), 256, ATTN_SMEM2>>>(
        mask, kpm,
        ph + 0 * PN, pl + 0 * PN,
        ph + 1 * PN, pl + 1 * PN,
        ph + 2 * PN, pl + 2 * PN,
        ao);

    tc_gemm5<0><<<ggrid, 256, GEMM5_SMEM>>>(ao, Wout, bout, 1.0f, out, nullptr);
}

// round 13
// speedup vs baseline: 2.1143x; 1.0881x over previous
#include <cuda_runtime.h>
#include <cuda_fp16.h>
#include <cstdint>

#define BB 4
#define TT 2048
#define SS 2048
#define CC 1024
#define HH 16
#define DD 64
#define SCALE_F 0.125f
#define MT (BB * TT)

typedef unsigned long long u64;
typedef unsigned int u32;
typedef unsigned short u16;

// ---------------------------------------------------------------------------
// Scratch (allocation-free rule: __device__ globals)
// ---------------------------------------------------------------------------
__device__ u16 g_ph[3][BB * HH * TT * DD]; // projected q,k,v f16 hi (B,H,T,D)
__device__ u16 g_pl[3][BB * HH * TT * DD]; // f16 lo (k,v only; q unused)
__device__ u16 g_ao[MT * CC];              // attn out f16 (B,T,C)
__device__ int g_flags;                    // bit0: mask nonzero, bit1: kpm any

// ---------------------------------------------------------------------------
// helpers
// ---------------------------------------------------------------------------
__device__ __forceinline__ u32 smem_u32(const void* p) {
    u32 a;
    asm("{ .reg .u64 t; cvta.to.shared.u64 t, %1; cvt.u32.u64 %0, t; }" : "=r"(a) : "l"(p));
    return a;
}
__device__ __forceinline__ void ldsm4(u32 addr, u32* r) {
    asm volatile("ldmatrix.sync.aligned.m8n8.x4.shared.b16 {%0,%1,%2,%3},[%4];"
                 : "=r"(r[0]), "=r"(r[1]), "=r"(r[2]), "=r"(r[3]) : "r"(addr));
}
__device__ __forceinline__ void ldsm4t(u32 addr, u32* r) {
    asm volatile("ldmatrix.sync.aligned.m8n8.x4.trans.shared.b16 {%0,%1,%2,%3},[%4];"
                 : "=r"(r[0]), "=r"(r[1]), "=r"(r[2]), "=r"(r[3]) : "r"(addr));
}
__device__ __forceinline__ void mma_f16(float* c, const u32* a, const u32* b) {
    asm volatile(
        "mma.sync.aligned.m16n8k16.row.col.f32.f16.f16.f32 "
        "{%0,%1,%2,%3},{%4,%5,%6,%7},{%8,%9},{%0,%1,%2,%3};"
        : "+f"(c[0]), "+f"(c[1]), "+f"(c[2]), "+f"(c[3])
        : "r"(a[0]), "r"(a[1]), "r"(a[2]), "r"(a[3]), "r"(b[0]), "r"(b[1]));
}
__device__ __forceinline__ u32 f16pair(float lo, float hi) {
    u32 r; asm("cvt.rn.f16x2.f32 %0,%1,%2;" : "=r"(r) : "f"(hi), "f"(lo)); return r;
}
__device__ __forceinline__ void h2unpack(u32 v, float& lo, float& hi) {
    asm("{.reg .b16 l,h; mov.b32 {l,h}, %2; cvt.f32.f16 %0, l; cvt.f32.f16 %1, h;}"
        : "=f"(lo), "=f"(hi) : "r"(v));
}
__device__ __forceinline__ void cpa16(u32 dst, const void* src) {
    asm volatile("cp.async.cg.shared.global [%0], [%1], 16;" :: "r"(dst), "l"(src));
}
__device__ __forceinline__ void cpa_commit() {
    asm volatile("cp.async.commit_group;" ::: "memory");
}
template <int N>
__device__ __forceinline__ void cpa_wait() {
    asm volatile("cp.async.wait_group %0;" :: "n"(N) : "memory");
}
// f16 split: hi = rn f16, lo = rn f16 of residual
__device__ __forceinline__ void split2_f16(float x, float y, u32& hi, u32& lo) {
    hi = f16pair(x, y);
    float hx, hy; h2unpack(hi, hx, hy);
    lo = f16pair(x - hx, y - hy);
}

// ---------------------------------------------------------------------------
// Mask content check
// ---------------------------------------------------------------------------
__global__ void mask_check(const float* __restrict__ mask,
                           const unsigned char* __restrict__ kpm)
{
    int idx = blockIdx.x * blockDim.x + threadIdx.x;
    int stride = gridDim.x * blockDim.x;
    int any_m = 0;
    const float4* m4 = (const float4*)mask;
    for (int i = idx; i < (TT * SS) / 4; i += stride) {
        float4 v = __ldg(m4 + i);
        any_m |= (v.x != 0.f) | (v.y != 0.f) | (v.z != 0.f) | (v.w != 0.f);
    }
    int any_k = 0;
    const uint4* k4 = (const uint4*)kpm;
    for (int i = idx; i < (BB * SS) / 16; i += stride) {
        uint4 v = __ldg(k4 + i);
        any_k |= ((v.x | v.y | v.z | v.w) != 0u);
    }
    if (__any_sync(0xffffffffu, any_m) && (threadIdx.x & 31) == 0) atomicOr(&g_flags, 1);
    if (__any_sync(0xffffffffu, any_k) && (threadIdx.x & 31) == 0) atomicOr(&g_flags, 2);
}

// ---------------------------------------------------------------------------
// f16x2 GEMM: out = A @ W^T + bias. A single f16 (rn), W split f16 hi+lo:
// 2 MMAs per fragment. 128x128 tile, 256 thr, 2 CTA/SM, K-chunks of 64.
// MODE 1: A fp32; scatter f16 hi/lo split to (B,H,T,D) * scale.
// MODE 2: A fp32; scatter f16 SINGLE (rn) to (B,H,T,D) * scale.
// MODE 0: A f16; fp32 row-major + bias.
// smem: Af[128][72]f16 @0, Bhi @18432, Blo @36864 (row stride 144B).
// ---------------------------------------------------------------------------
#define GST5 144
#define GT5 (128 * GST5)          // 18432
#define GEMM5_SMEM (3 * GT5)      // 55296

template <int MODE>
__global__ __launch_bounds__(256, 2) void tc_gemm5(
    const void* __restrict__ A_, const float* __restrict__ W,
    const float* __restrict__ bias, float scale,
    void* __restrict__ oa, void* __restrict__ ob)
{
    extern __shared__ __align__(128) char dsm[];
    char* Af = dsm;
    char* Bhi = dsm + GT5;
    char* Blo = dsm + 2 * GT5;
    const u32 sb = smem_u32(dsm);

    const int tid = threadIdx.x;
    const int lane = tid & 31;
    const int wid = tid >> 5;
    const int wm = wid & 3;
    const int wn = wid >> 2;
    const int bm = blockIdx.y * 128, bn = blockIdx.x * 128;
    const int K = CC;

    const u32 aOff = (u32)((wm * 32 + (lane & 15)) * GST5 + (lane >> 4) * 16);
    const u32 bRow = (u32)(((lane >> 4) << 3) + (lane & 7));
    const u32 bOff = (u32)((wn * 64 + bRow) * GST5 + ((lane >> 3) & 1) * 16);

    float acc[2][8][4];
#pragma unroll
    for (int i = 0; i < 2; i++)
#pragma unroll
        for (int j = 0; j < 8; j++)
#pragma unroll
            for (int q = 0; q < 4; q++) acc[i][j][q] = 0.f;

    const float* Wp = W + (size_t)bn * K;

    for (int k0 = 0; k0 < K; k0 += 64) {
#pragma unroll
        for (int i = 0; i < 8; i++) {
            int f = tid + i * 256;
            int r = f >> 4, kq = (f & 15) << 2;
            u32 soff = (u32)(r * GST5 + kq * 2);
            if (MODE != 0) {
                const float* Ap = (const float*)A_ + (size_t)bm * K;
                float4 a = __ldg((const float4*)(Ap + (size_t)r * K + k0 + kq));
                u32 p01 = f16pair(a.x, a.y);
                u32 p23 = f16pair(a.z, a.w);
                *(uint2*)(Af + soff) = make_uint2(p01, p23);
            } else {
                const u16* Ap = (const u16*)A_ + (size_t)bm * K;
                uint2 v = __ldg((const uint2*)(Ap + (size_t)r * K + k0 + kq));
                *(uint2*)(Af + soff) = v;
            }
            float4 w = __ldg((const float4*)(Wp + (size_t)r * K + k0 + kq));
            u32 h01, l01, h23, l23;
            split2_f16(w.x, w.y, h01, l01);
            split2_f16(w.z, w.w, h23, l23);
            *(uint2*)(Bhi + soff) = make_uint2(h01, h23);
            *(uint2*)(Blo + soff) = make_uint2(l01, l23);
        }
        __syncthreads();

        const u32 aA = sb + aOff;
        const u32 bHA = sb + GT5 + bOff;
        const u32 bLA = sb + 2 * GT5 + bOff;
#pragma unroll
        for (int ks = 0; ks < 4; ks++) {
            u32 ah[2][4];
#pragma unroll
            for (int mf = 0; mf < 2; mf++)
                ldsm4(aA + mf * 2304 + ks * 32, ah[mf]);
#pragma unroll
            for (int ng = 0; ng < 4; ng++) {
                u32 bh[4], bl[4];
                ldsm4(bHA + ng * 2304 + ks * 32, bh);
                ldsm4(bLA + ng * 2304 + ks * 32, bl);
#pragma unroll
                for (int half = 0; half < 2; half++) {
                    int nf = ng * 2 + half;
#pragma unroll
                    for (int mf = 0; mf < 2; mf++) {
                        mma_f16(acc[mf][nf], ah[mf], &bh[half * 2]);
                        mma_f16(acc[mf][nf], ah[mf], &bl[half * 2]);
                    }
                }
            }
        }
        __syncthreads();
    }

#pragma unroll
    for (int mf = 0; mf < 2; mf++) {
#pragma unroll
        for (int nf = 0; nf < 8; nf++) {
            int m = bm + wm * 32 + mf * 16 + (lane >> 2);
            int n = bn + wn * 64 + nf * 8 + (lane & 3) * 2;
            float b0 = __ldg(bias + n), b1 = __ldg(bias + n + 1);
            if (MODE == 0) {
                float* out = (float*)oa;
                *(float2*)(out + (size_t)m * CC + n) =
                    make_float2(acc[mf][nf][0] + b0, acc[mf][nf][1] + b1);
                *(float2*)(out + (size_t)(m + 8) * CC + n) =
                    make_float2(acc[mf][nf][2] + b0, acc[mf][nf][3] + b1);
            } else {
                u32* oh = (u32*)oa;
                u32* ol = (u32*)ob;
                int h = n >> 6, d = n & (DD - 1);
                float v0 = (acc[mf][nf][0] + b0) * scale;
                float v1 = (acc[mf][nf][1] + b1) * scale;
                float v2 = (acc[mf][nf][2] + b0) * scale;
                float v3 = (acc[mf][nf][3] + b1) * scale;
                int b_ = m >> 11, t = m & (TT - 1);
                size_t idx0 = ((((size_t)b_ * HH + h) * TT + t) * DD + d) >> 1;
                int m1 = m + 8;
                int b1_ = m1 >> 11, t1 = m1 & (TT - 1);
                size_t idx1 = ((((size_t)b1_ * HH + h) * TT + t1) * DD + d) >> 1;
                if (MODE == 1) {
                    u32 hi, lo;
                    split2_f16(v0, v1, hi, lo);
                    oh[idx0] = hi; ol[idx0] = lo;
                    split2_f16(v2, v3, hi, lo);
                    oh[idx1] = hi; ol[idx1] = lo;
                } else {
                    oh[idx0] = f16pair(v0, v1);
                    oh[idx1] = f16pair(v2, v3);
                }
            }
        }
    }
}

// ---------------------------------------------------------------------------
// Tensor-core flash attention. Q single f16 (2-MMA QK), K hi+lo, V hi+lo,
// P f16-hi (2-MMA PV). Epilogue -> f16 single.
// smem: Qf[128][72] @0 (18432); KV buffers @18432 + buf*36864:
//   Khi +0, Klo +9216, Vhi +18432, Vlo +27648.  Total 92160.
// ---------------------------------------------------------------------------
#define AST 144
#define AKV0 18432
#define AKVB 36864
#define ATTN_SMEM3 92160

__global__ __launch_bounds__(256, 2) void attn_tc3(
    const float* __restrict__ mask, const unsigned char* __restrict__ kpm,
    const u16* __restrict__ qf,
    const u16* __restrict__ kh, const u16* __restrict__ kl,
    const u16* __restrict__ vh, const u16* __restrict__ vl,
    u16* __restrict__ ao_out)
{
    extern __shared__ __align__(128) char smr[];
    const u32 sb = smem_u32(smr);

    const int tid = threadIdx.x;
    const int lane = tid & 31;
    const int w = tid >> 5;
    const int tblk = blockIdx.x * 128;
    const int h = blockIdx.y, b = blockIdx.z;
    const float NEGINF = __int_as_float(0xff800000);

    const int flags = g_flags;
    const bool mflag = (flags & 1) != 0;
    const bool kflag = (flags & 2) != 0;

    const size_t baseq = (((size_t)b * HH + h) * TT + tblk) * DD;
    const size_t basekv = ((size_t)b * HH + h) * (size_t)SS * DD;

    // prologue: Q tile (single f16)
    {
        const u16* src = qf + baseq;
#pragma unroll
        for (int i = 0; i < 4; i++) {
            int s = tid + i * 256;
            int r = s >> 3, j = s & 7;
            cpa16(sb + r * AST + j * 16, src + (size_t)r * DD + j * 8);
        }
    }
    cpa_commit();

    auto issueKV = [&](int s0, int buf) {
        const u16* srcs[4] = { kh + basekv, kl + basekv, vh + basekv, vl + basekv };
        u32 dbase = sb + AKV0 + buf * AKVB;
#pragma unroll
        for (int t = 0; t < 4; t++) {
#pragma unroll
            for (int i = 0; i < 2; i++) {
                int s = tid + i * 256;
                int r = s >> 3, j = s & 7;
                cpa16(dbase + t * 9216 + r * AST + j * 16,
                      srcs[t] + (size_t)(s0 + r) * DD + j * 8);
            }
        }
        cpa_commit();
    };
    issueKV(0, 0);

    const u32 aQ = sb + (u32)((w * 16 + (lane & 15)) * AST + (lane >> 4) * 16);
    const u32 bKoff = (u32)((((lane >> 4) << 3) + (lane & 7)) * AST + ((lane >> 3) & 1) * 16);
    const u32 bVoff = (u32)((lane & 15) * AST + (lane >> 4) * 16);

    const int row0 = tblk + w * 16 + (lane >> 2);
    const float* mrow0 = mask + (size_t)row0 * SS;
    const float* mrow1 = mrow0 + 8 * (size_t)SS;

    float O[8][4];
#pragma unroll
    for (int i = 0; i < 8; i++)
#pragma unroll
        for (int j = 0; j < 4; j++) O[i][j] = 0.f;
    float l0 = 0.f, l1 = 0.f, m0 = NEGINF, m1 = NEGINF;

    int buf = 0;
    for (int c = 0; c < SS / 64; c++) {
        const int s0 = c * 64;
        cpa_wait<0>();
        __syncthreads();
        if (c + 1 < SS / 64) issueKV(s0 + 64, buf ^ 1);

        const u32 kvb = sb + AKV0 + buf * AKVB;
        const u32 bK = kvb + bKoff;
        const u32 bV = kvb + 18432 + bVoff;

        float sacc[8][4];
#pragma unroll
        for (int i = 0; i < 8; i++)
#pragma unroll
            for (int j = 0; j < 4; j++) sacc[i][j] = 0.f;
#pragma unroll
        for (int ks = 0; ks < 4; ks++) {
            u32 ahf[4];
            ldsm4(aQ + ks * 32, ahf);
#pragma unroll
            for (int pg = 0; pg < 2; pg++) {
                u32 bh[2][4], bl[2][4];
#pragma unroll
                for (int g = 0; g < 2; g++) {
                    ldsm4(bK + (pg * 2 + g) * 2304 + ks * 32, bh[g]);
                    ldsm4(bK + 9216 + (pg * 2 + g) * 2304 + ks * 32, bl[g]);
                }
#pragma unroll
                for (int g = 0; g < 2; g++)
#pragma unroll
                    for (int half = 0; half < 2; half++)
                        mma_f16(sacc[(pg * 2 + g) * 2 + half], ahf, &bh[g][half * 2]);
#pragma unroll
                for (int g = 0; g < 2; g++)
#pragma unroll
                    for (int half = 0; half < 2; half++)
                        mma_f16(sacc[(pg * 2 + g) * 2 + half], ahf, &bl[g][half * 2]);
            }
        }

        if (kflag) {
#pragma unroll
            for (int nf = 0; nf < 8; nf++) {
                int col = s0 + nf * 8 + (lane & 3) * 2;
                float k0 = kpm[(size_t)b * SS + col] ? NEGINF : 0.f;
                float k1 = kpm[(size_t)b * SS + col + 1] ? NEGINF : 0.f;
                sacc[nf][0] += k0; sacc[nf][1] += k1;
                sacc[nf][2] += k0; sacc[nf][3] += k1;
            }
        }
        if (mflag) {
#pragma unroll
            for (int nf = 0; nf < 8; nf++) {
                int col = s0 + nf * 8 + (lane & 3) * 2;
                float2 mv0 = __ldg((const float2*)(mrow0 + col));
                float2 mv1 = __ldg((const float2*)(mrow1 + col));
                sacc[nf][0] += mv0.x; sacc[nf][1] += mv0.y;
                sacc[nf][2] += mv1.x; sacc[nf][3] += mv1.y;
            }
        }

        float cm0 = NEGINF, cm1 = NEGINF;
#pragma unroll
        for (int nf = 0; nf < 8; nf++) {
            cm0 = fmaxf(cm0, fmaxf(sacc[nf][0], sacc[nf][1]));
            cm1 = fmaxf(cm1, fmaxf(sacc[nf][2], sacc[nf][3]));
        }
        cm0 = fmaxf(cm0, __shfl_xor_sync(0xffffffffu, cm0, 1));
        cm0 = fmaxf(cm0, __shfl_xor_sync(0xffffffffu, cm0, 2));
        cm1 = fmaxf(cm1, __shfl_xor_sync(0xffffffffu, cm1, 1));
        cm1 = fmaxf(cm1, __shfl_xor_sync(0xffffffffu, cm1, 2));

        float mn0 = fmaxf(m0, cm0), mn1 = fmaxf(m1, cm1);
        float c0 = __expf(m0 - mn0), c1 = __expf(m1 - mn1);
        m0 = mn0; m1 = mn1;
        l0 *= c0; l1 *= c1;
#pragma unroll
        for (int nf = 0; nf < 8; nf++) {
            O[nf][0] *= c0; O[nf][1] *= c0;
            O[nf][2] *= c1; O[nf][3] *= c1;
        }

        u32 phi[8][2];
        float rs0 = 0.f, rs1 = 0.f;
#pragma unroll
        for (int nf = 0; nf < 8; nf++) {
            float p0 = __expf(sacc[nf][0] - mn0);
            float p1 = __expf(sacc[nf][1] - mn0);
            float p2 = __expf(sacc[nf][2] - mn1);
            float p3 = __expf(sacc[nf][3] - mn1);
            rs0 += p0 + p1; rs1 += p2 + p3;
            phi[nf][0] = f16pair(p0, p1);
            phi[nf][1] = f16pair(p2, p3);
        }
        rs0 += __shfl_xor_sync(0xffffffffu, rs0, 1);
        rs0 += __shfl_xor_sync(0xffffffffu, rs0, 2);
        rs1 += __shfl_xor_sync(0xffffffffu, rs1, 1);
        rs1 += __shfl_xor_sync(0xffffffffu, rs1, 2);
        l0 += rs0; l1 += rs1;

#pragma unroll
        for (int ks = 0; ks < 4; ks++) {
            u32 ap[4] = {phi[2 * ks][0], phi[2 * ks][1],
                         phi[2 * ks + 1][0], phi[2 * ks + 1][1]};
#pragma unroll
            for (int pd = 0; pd < 2; pd++) {
                u32 bh[2][4], bl[2][4];
#pragma unroll
                for (int g = 0; g < 2; g++) {
                    ldsm4t(bV + ks * 2304 + (pd * 2 + g) * 32, bh[g]);
                    ldsm4t(bV + 9216 + ks * 2304 + (pd * 2 + g) * 32, bl[g]);
                }
#pragma unroll
                for (int g = 0; g < 2; g++)
#pragma unroll
                    for (int half = 0; half < 2; half++)
                        mma_f16(O[(pd * 2 + g) * 2 + half], ap, &bh[g][half * 2]);
#pragma unroll
                for (int g = 0; g < 2; g++)
#pragma unroll
                    for (int half = 0; half < 2; half++)
                        mma_f16(O[(pd * 2 + g) * 2 + half], ap, &bl[g][half * 2]);
            }
        }
        buf ^= 1;
    }

    // epilogue: normalize, write f16 (rn) to (B,T,C)
    float i0 = __fdividef(1.f, l0), i1 = __fdividef(1.f, l1);
    size_t base0 = ((size_t)b * TT + row0) * CC + h * DD + (lane & 3) * 2;
    size_t base1 = base0 + 8 * (size_t)CC;
    u32* oa = (u32*)ao_out;
#pragma unroll
    for (int nf = 0; nf < 8; nf++) {
        oa[(base0 + nf * 8) >> 1] = f16pair(O[nf][0] * i0, O[nf][1] * i0);
        oa[(base1 + nf * 8) >> 1] = f16pair(O[nf][2] * i1, O[nf][3] * i1);
    }
}

// ---------------------------------------------------------------------------
// Launch
// ---------------------------------------------------------------------------
extern "C" void kernel_launch(void* const* d_in, const int* in_sizes, int n_in,
                              void* d_out, int out_size)
{
    (void)in_sizes; (void)n_in; (void)out_size;
    const float* query = (const float*)d_in[0];
    const float* key   = (const float*)d_in[1];
    const float* value = (const float*)d_in[2];
    const float* mask  = (const float*)d_in[3];
    const unsigned char* kpm = (const unsigned char*)d_in[4];
    const float* Wq = (const float*)d_in[5];
    const float* bq = (const float*)d_in[6];
    const float* Wk = (const float*)d_in[7];
    const float* bk = (const float*)d_in[8];
    const float* Wv = (const float*)d_in[9];
    const float* bv = (const float*)d_in[10];
    const float* Wout = (const float*)d_in[11];
    const float* bout = (const float*)d_in[12];
    float* out = (float*)d_out;

    u16 *ph, *pl, *ao;
    int* fp;
    cudaGetSymbolAddress((void**)&ph, g_ph);
    cudaGetSymbolAddress((void**)&pl, g_pl);
    cudaGetSymbolAddress((void**)&ao, g_ao);
    cudaGetSymbolAddress((void**)&fp, g_flags);

    const size_t PN = (size_t)BB * HH * TT * DD;

    cudaFuncSetAttribute(tc_gemm5<0>, cudaFuncAttributeMaxDynamicSharedMemorySize, GEMM5_SMEM);
    cudaFuncSetAttribute(tc_gemm5<1>, cudaFuncAttributeMaxDynamicSharedMemorySize, GEMM5_SMEM);
    cudaFuncSetAttribute(tc_gemm5<2>, cudaFuncAttributeMaxDynamicSharedMemorySize, GEMM5_SMEM);
    cudaFuncSetAttribute(attn_tc3, cudaFuncAttributeMaxDynamicSharedMemorySize, ATTN_SMEM3);

    cudaMemsetAsync(fp, 0, sizeof(int));
    mask_check<<<1024, 256>>>(mask, kpm);

    dim3 ggrid(CC / 128, MT / 128);   // (8, 64)
    // Q: single f16 output (2-MMA QK consumes it directly)
    tc_gemm5<2><<<ggrid, 256, GEMM5_SMEM>>>(query, Wq, bq, SCALE_F,
                                            ph + 0 * PN, nullptr);
    tc_gemm5<1><<<ggrid, 256, GEMM5_SMEM>>>(key,   Wk, bk, 1.0f,
                                            ph + 1 * PN, pl + 1 * PN);
    tc_gemm5<1><<<ggrid, 256, GEMM5_SMEM>>>(value, Wv, bv, 1.0f,
                                            ph + 2 * PN, pl + 2 * PN);

    attn_tc3<<<dim3(TT / 128, HH, BB), 256, ATTN_SMEM3>>>(
        mask, kpm,
        ph + 0 * PN,
        ph + 1 * PN, pl + 1 * PN,
        ph + 2 * PN, pl + 2 * PN,
        ao);

    tc_gemm5<0><<<ggrid, 256, GEMM5_SMEM>>>(ao, Wout, bout, 1.0f, out, nullptr);
}

// round 14
// speedup vs baseline: 2.9039x; 1.3734x over previous
#include <cuda_runtime.h>
#include <cuda_fp16.h>
#include <cstdint>

#define BB 4
#define TT 2048
#define SS 2048
#define CC 1024
#define HH 16
#define DD 64
#define SCALE_F 0.125f
#define MT (BB * TT)

typedef unsigned long long u64;
typedef unsigned int u32;
typedef unsigned short u16;

// ---------------------------------------------------------------------------
// Scratch (allocation-free rule: __device__ globals)
// ---------------------------------------------------------------------------
__device__ u16 g_ph[3][BB * HH * TT * DD]; // projected q,k,v f16 (B,H,T,D)
__device__ u16 g_ao[MT * CC];              // attn out f16 (B,T,C)
__device__ int g_flags;                    // bit0: mask nonzero, bit1: kpm any

// ---------------------------------------------------------------------------
// helpers
// ---------------------------------------------------------------------------
__device__ __forceinline__ u32 smem_u32(const void* p) {
    u32 a;
    asm("{ .reg .u64 t; cvta.to.shared.u64 t, %1; cvt.u32.u64 %0, t; }" : "=r"(a) : "l"(p));
    return a;
}
__device__ __forceinline__ void ldsm4(u32 addr, u32* r) {
    asm volatile("ldmatrix.sync.aligned.m8n8.x4.shared.b16 {%0,%1,%2,%3},[%4];"
                 : "=r"(r[0]), "=r"(r[1]), "=r"(r[2]), "=r"(r[3]) : "r"(addr));
}
__device__ __forceinline__ void ldsm4t(u32 addr, u32* r) {
    asm volatile("ldmatrix.sync.aligned.m8n8.x4.trans.shared.b16 {%0,%1,%2,%3},[%4];"
                 : "=r"(r[0]), "=r"(r[1]), "=r"(r[2]), "=r"(r[3]) : "r"(addr));
}
__device__ __forceinline__ void mma_f16(float* c, const u32* a, const u32* b) {
    asm volatile(
        "mma.sync.aligned.m16n8k16.row.col.f32.f16.f16.f32 "
        "{%0,%1,%2,%3},{%4,%5,%6,%7},{%8,%9},{%0,%1,%2,%3};"
        : "+f"(c[0]), "+f"(c[1]), "+f"(c[2]), "+f"(c[3])
        : "r"(a[0]), "r"(a[1]), "r"(a[2]), "r"(a[3]), "r"(b[0]), "r"(b[1]));
}
__device__ __forceinline__ u32 f16pair(float lo, float hi) {
    u32 r; asm("cvt.rn.f16x2.f32 %0,%1,%2;" : "=r"(r) : "f"(hi), "f"(lo)); return r;
}
__device__ __forceinline__ void h2unpack(u32 v, float& lo, float& hi) {
    asm("{.reg .b16 l,h; mov.b32 {l,h}, %2; cvt.f32.f16 %0, l; cvt.f32.f16 %1, h;}"
        : "=f"(lo), "=f"(hi) : "r"(v));
}
__device__ __forceinline__ void cpa16(u32 dst, const void* src) {
    asm volatile("cp.async.cg.shared.global [%0], [%1], 16;" :: "r"(dst), "l"(src));
}
__device__ __forceinline__ void cpa_commit() {
    asm volatile("cp.async.commit_group;" ::: "memory");
}
template <int N>
__device__ __forceinline__ void cpa_wait() {
    asm volatile("cp.async.wait_group %0;" :: "n"(N) : "memory");
}
// f16 split: hi = rn f16, lo = rn f16 of residual
__device__ __forceinline__ void split2_f16(float x, float y, u32& hi, u32& lo) {
    hi = f16pair(x, y);
    float hx, hy; h2unpack(hi, hx, hy);
    lo = f16pair(x - hx, y - hy);
}

// ---------------------------------------------------------------------------
// Mask content check
// ---------------------------------------------------------------------------
__global__ void mask_check(const float* __restrict__ mask,
                           const unsigned char* __restrict__ kpm)
{
    int idx = blockIdx.x * blockDim.x + threadIdx.x;
    int stride = gridDim.x * blockDim.x;
    int any_m = 0;
    const float4* m4 = (const float4*)mask;
    for (int i = idx; i < (TT * SS) / 4; i += stride) {
        float4 v = __ldg(m4 + i);
        any_m |= (v.x != 0.f) | (v.y != 0.f) | (v.z != 0.f) | (v.w != 0.f);
    }
    int any_k = 0;
    const uint4* k4 = (const uint4*)kpm;
    for (int i = idx; i < (BB * SS) / 16; i += stride) {
        uint4 v = __ldg(k4 + i);
        any_k |= ((v.x | v.y | v.z | v.w) != 0u);
    }
    if (__any_sync(0xffffffffu, any_m) && (threadIdx.x & 31) == 0) atomicOr(&g_flags, 1);
    if (__any_sync(0xffffffffu, any_k) && (threadIdx.x & 31) == 0) atomicOr(&g_flags, 2);
}

// ---------------------------------------------------------------------------
// f16 GEMM: out = A @ W^T + bias. 128x128 tile, 256 thr, 2 CTA/SM, K-chunks 64.
// TERMS=1: W single f16 (1 MMA/frag). TERMS=2: W split hi+lo (2 MMA/frag).
// MODE 2: A fp32 in; scatter f16 single to (B,H,T,D) * scale.
// MODE 0: A f16 in; fp32 row-major + bias out.
// smem: Af[128][72]f16 @0, Bhi @GT5, (Blo @2*GT5 if TERMS==2); stride 144B.
// ---------------------------------------------------------------------------
#define GST5 144
#define GT5 (128 * GST5)          // 18432

template <int MODE, int TERMS>
__global__ __launch_bounds__(256, 2) void tc_gemm6(
    const void* __restrict__ A_, const float* __restrict__ W,
    const float* __restrict__ bias, float scale,
    void* __restrict__ oa)
{
    extern __shared__ __align__(128) char dsm[];
    char* Af = dsm;
    char* Bhi = dsm + GT5;
    char* Blo = dsm + 2 * GT5;
    const u32 sb = smem_u32(dsm);

    const int tid = threadIdx.x;
    const int lane = tid & 31;
    const int wid = tid >> 5;
    const int wm = wid & 3;
    const int wn = wid >> 2;
    const int bm = blockIdx.y * 128, bn = blockIdx.x * 128;
    const int K = CC;

    const u32 aOff = (u32)((wm * 32 + (lane & 15)) * GST5 + (lane >> 4) * 16);
    const u32 bRow = (u32)(((lane >> 4) << 3) + (lane & 7));
    const u32 bOff = (u32)((wn * 64 + bRow) * GST5 + ((lane >> 3) & 1) * 16);

    float acc[2][8][4];
#pragma unroll
    for (int i = 0; i < 2; i++)
#pragma unroll
        for (int j = 0; j < 8; j++)
#pragma unroll
            for (int q = 0; q < 4; q++) acc[i][j][q] = 0.f;

    const float* Wp = W + (size_t)bn * K;

    for (int k0 = 0; k0 < K; k0 += 64) {
#pragma unroll
        for (int i = 0; i < 8; i++) {
            int f = tid + i * 256;
            int r = f >> 4, kq = (f & 15) << 2;
            u32 soff = (u32)(r * GST5 + kq * 2);
            if (MODE != 0) {
                const float* Ap = (const float*)A_ + (size_t)bm * K;
                float4 a = __ldg((const float4*)(Ap + (size_t)r * K + k0 + kq));
                *(uint2*)(Af + soff) = make_uint2(f16pair(a.x, a.y), f16pair(a.z, a.w));
            } else {
                const u16* Ap = (const u16*)A_ + (size_t)bm * K;
                uint2 v = __ldg((const uint2*)(Ap + (size_t)r * K + k0 + kq));
                *(uint2*)(Af + soff) = v;
            }
            float4 w = __ldg((const float4*)(Wp + (size_t)r * K + k0 + kq));
            if (TERMS == 2) {
                u32 h01, l01, h23, l23;
                split2_f16(w.x, w.y, h01, l01);
                split2_f16(w.z, w.w, h23, l23);
                *(uint2*)(Bhi + soff) = make_uint2(h01, h23);
                *(uint2*)(Blo + soff) = make_uint2(l01, l23);
            } else {
                *(uint2*)(Bhi + soff) = make_uint2(f16pair(w.x, w.y), f16pair(w.z, w.w));
            }
        }
        __syncthreads();

        const u32 aA = sb + aOff;
        const u32 bHA = sb + GT5 + bOff;
        const u32 bLA = sb + 2 * GT5 + bOff;
#pragma unroll
        for (int ks = 0; ks < 4; ks++) {
            u32 ah[2][4];
#pragma unroll
            for (int mf = 0; mf < 2; mf++)
                ldsm4(aA + mf * 2304 + ks * 32, ah[mf]);
#pragma unroll
            for (int ng = 0; ng < 4; ng++) {
                u32 bh[4], bl[4];
                ldsm4(bHA + ng * 2304 + ks * 32, bh);
                if (TERMS == 2) ldsm4(bLA + ng * 2304 + ks * 32, bl);
#pragma unroll
                for (int half = 0; half < 2; half++) {
                    int nf = ng * 2 + half;
#pragma unroll
                    for (int mf = 0; mf < 2; mf++) {
                        mma_f16(acc[mf][nf], ah[mf], &bh[half * 2]);
                        if (TERMS == 2) mma_f16(acc[mf][nf], ah[mf], &bl[half * 2]);
                    }
                }
            }
        }
        __syncthreads();
    }

#pragma unroll
    for (int mf = 0; mf < 2; mf++) {
#pragma unroll
        for (int nf = 0; nf < 8; nf++) {
            int m = bm + wm * 32 + mf * 16 + (lane >> 2);
            int n = bn + wn * 64 + nf * 8 + (lane & 3) * 2;
            float b0 = __ldg(bias + n), b1 = __ldg(bias + n + 1);
            if (MODE == 0) {
                float* out = (float*)oa;
                *(float2*)(out + (size_t)m * CC + n) =
                    make_float2(acc[mf][nf][0] + b0, acc[mf][nf][1] + b1);
                *(float2*)(out + (size_t)(m + 8) * CC + n) =
                    make_float2(acc[mf][nf][2] + b0, acc[mf][nf][3] + b1);
            } else {
                u32* oh = (u32*)oa;
                int h = n >> 6, d = n & (DD - 1);
                float v0 = (acc[mf][nf][0] + b0) * scale;
                float v1 = (acc[mf][nf][1] + b1) * scale;
                float v2 = (acc[mf][nf][2] + b0) * scale;
                float v3 = (acc[mf][nf][3] + b1) * scale;
                int b_ = m >> 11, t = m & (TT - 1);
                size_t idx0 = ((((size_t)b_ * HH + h) * TT + t) * DD + d) >> 1;
                int m1 = m + 8;
                int b1_ = m1 >> 11, t1 = m1 & (TT - 1);
                size_t idx1 = ((((size_t)b1_ * HH + h) * TT + t1) * DD + d) >> 1;
                oh[idx0] = f16pair(v0, v1);
                oh[idx1] = f16pair(v2, v3);
            }
        }
    }
}

// ---------------------------------------------------------------------------
// Tensor-core flash attention, all-single-f16 operands.
// Q, K, V single f16: QK 1 MMA/frag, PV 1 MMA/frag (P f16-hi).
// smem: Qf[128][72] @0 (18432); KV buffers @18432 + buf*18432:
//   Kf +0 (9216), Vf +9216.  Total 55296.
// ---------------------------------------------------------------------------
#define AST 144
#define AKV0 18432
#define AKVB 18432
#define ATTN_SMEM4 55296

__global__ __launch_bounds__(256, 2) void attn_tc4(
    const float* __restrict__ mask, const unsigned char* __restrict__ kpm,
    const u16* __restrict__ qf, const u16* __restrict__ kf,
    const u16* __restrict__ vf, u16* __restrict__ ao_out)
{
    extern __shared__ __align__(128) char smr[];
    const u32 sb = smem_u32(smr);

    const int tid = threadIdx.x;
    const int lane = tid & 31;
    const int w = tid >> 5;
    const int tblk = blockIdx.x * 128;
    const int h = blockIdx.y, b = blockIdx.z;
    const float NEGINF = __int_as_float(0xff800000);

    const int flags = g_flags;
    const bool mflag = (flags & 1) != 0;
    const bool kflag = (flags & 2) != 0;

    const size_t baseq = (((size_t)b * HH + h) * TT + tblk) * DD;
    const size_t basekv = ((size_t)b * HH + h) * (size_t)SS * DD;

    // prologue: Q tile (single f16)
    {
        const u16* src = qf + baseq;
#pragma unroll
        for (int i = 0; i < 4; i++) {
            int s = tid + i * 256;
            int r = s >> 3, j = s & 7;
            cpa16(sb + r * AST + j * 16, src + (size_t)r * DD + j * 8);
        }
    }
    cpa_commit();

    auto issueKV = [&](int s0, int buf) {
        u32 dbase = sb + AKV0 + buf * AKVB;
        const u16* ks = kf + basekv;
        const u16* vs = vf + basekv;
#pragma unroll
        for (int i = 0; i < 2; i++) {
            int s = tid + i * 256;
            int r = s >> 3, j = s & 7;
            cpa16(dbase + r * AST + j * 16, ks + (size_t)(s0 + r) * DD + j * 8);
            cpa16(dbase + 9216 + r * AST + j * 16, vs + (size_t)(s0 + r) * DD + j * 8);
        }
        cpa_commit();
    };
    issueKV(0, 0);

    const u32 aQ = sb + (u32)((w * 16 + (lane & 15)) * AST + (lane >> 4) * 16);
    const u32 bKoff = (u32)((((lane >> 4) << 3) + (lane & 7)) * AST + ((lane >> 3) & 1) * 16);
    const u32 bVoff = (u32)((lane & 15) * AST + (lane >> 4) * 16);

    const int row0 = tblk + w * 16 + (lane >> 2);
    const float* mrow0 = mask + (size_t)row0 * SS;
    const float* mrow1 = mrow0 + 8 * (size_t)SS;

    float O[8][4];
#pragma unroll
    for (int i = 0; i < 8; i++)
#pragma unroll
        for (int j = 0; j < 4; j++) O[i][j] = 0.f;
    float l0 = 0.f, l1 = 0.f, m0 = NEGINF, m1 = NEGINF;

    int buf = 0;
    for (int c = 0; c < SS / 64; c++) {
        const int s0 = c * 64;
        cpa_wait<0>();
        __syncthreads();
        if (c + 1 < SS / 64) issueKV(s0 + 64, buf ^ 1);

        const u32 kvb = sb + AKV0 + buf * AKVB;
        const u32 bK = kvb + bKoff;
        const u32 bV = kvb + 9216 + bVoff;

        // S = Q K^T (single f16)
        float sacc[8][4];
#pragma unroll
        for (int i = 0; i < 8; i++)
#pragma unroll
            for (int j = 0; j < 4; j++) sacc[i][j] = 0.f;
#pragma unroll
        for (int ks = 0; ks < 4; ks++) {
            u32 ahf[4];
            ldsm4(aQ + ks * 32, ahf);
#pragma unroll
            for (int pg = 0; pg < 2; pg++) {
                u32 bh[2][4];
#pragma unroll
                for (int g = 0; g < 2; g++)
                    ldsm4(bK + (pg * 2 + g) * 2304 + ks * 32, bh[g]);
#pragma unroll
                for (int g = 0; g < 2; g++)
#pragma unroll
                    for (int half = 0; half < 2; half++)
                        mma_f16(sacc[(pg * 2 + g) * 2 + half], ahf, &bh[g][half * 2]);
            }
        }

        if (kflag) {
#pragma unroll
            for (int nf = 0; nf < 8; nf++) {
                int col = s0 + nf * 8 + (lane & 3) * 2;
                float k0 = kpm[(size_t)b * SS + col] ? NEGINF : 0.f;
                float k1 = kpm[(size_t)b * SS + col + 1] ? NEGINF : 0.f;
                sacc[nf][0] += k0; sacc[nf][1] += k1;
                sacc[nf][2] += k0; sacc[nf][3] += k1;
            }
        }
        if (mflag) {
#pragma unroll
            for (int nf = 0; nf < 8; nf++) {
                int col = s0 + nf * 8 + (lane & 3) * 2;
                float2 mv0 = __ldg((const float2*)(mrow0 + col));
                float2 mv1 = __ldg((const float2*)(mrow1 + col));
                sacc[nf][0] += mv0.x; sacc[nf][1] += mv0.y;
                sacc[nf][2] += mv1.x; sacc[nf][3] += mv1.y;
            }
        }

        float cm0 = NEGINF, cm1 = NEGINF;
#pragma unroll
        for (int nf = 0; nf < 8; nf++) {
            cm0 = fmaxf(cm0, fmaxf(sacc[nf][0], sacc[nf][1]));
            cm1 = fmaxf(cm1, fmaxf(sacc[nf][2], sacc[nf][3]));
        }
        cm0 = fmaxf(cm0, __shfl_xor_sync(0xffffffffu, cm0, 1));
        cm0 = fmaxf(cm0, __shfl_xor_sync(0xffffffffu, cm0, 2));
        cm1 = fmaxf(cm1, __shfl_xor_sync(0xffffffffu, cm1, 1));
        cm1 = fmaxf(cm1, __shfl_xor_sync(0xffffffffu, cm1, 2));

        float mn0 = fmaxf(m0, cm0), mn1 = fmaxf(m1, cm1);
        float c0 = __expf(m0 - mn0), c1 = __expf(m1 - mn1);
        m0 = mn0; m1 = mn1;
        l0 *= c0; l1 *= c1;
#pragma unroll
        for (int nf = 0; nf < 8; nf++) {
            O[nf][0] *= c0; O[nf][1] *= c0;
            O[nf][2] *= c1; O[nf][3] *= c1;
        }

        u32 phi[8][2];
        float rs0 = 0.f, rs1 = 0.f;
#pragma unroll
        for (int nf = 0; nf < 8; nf++) {
            float p0 = __expf(sacc[nf][0] - mn0);
            float p1 = __expf(sacc[nf][1] - mn0);
            float p2 = __expf(sacc[nf][2] - mn1);
            float p3 = __expf(sacc[nf][3] - mn1);
            rs0 += p0 + p1; rs1 += p2 + p3;
            phi[nf][0] = f16pair(p0, p1);
            phi[nf][1] = f16pair(p2, p3);
        }
        rs0 += __shfl_xor_sync(0xffffffffu, rs0, 1);
        rs0 += __shfl_xor_sync(0xffffffffu, rs0, 2);
        rs1 += __shfl_xor_sync(0xffffffffu, rs1, 1);
        rs1 += __shfl_xor_sync(0xffffffffu, rs1, 2);
        l0 += rs0; l1 += rs1;

        // O += P V (single f16)
#pragma unroll
        for (int ks = 0; ks < 4; ks++) {
            u32 ap[4] = {phi[2 * ks][0], phi[2 * ks][1],
                         phi[2 * ks + 1][0], phi[2 * ks + 1][1]};
#pragma unroll
            for (int pd = 0; pd < 2; pd++) {
                u32 bh[2][4];
#pragma unroll
                for (int g = 0; g < 2; g++)
                    ldsm4t(bV + ks * 2304 + (pd * 2 + g) * 32, bh[g]);
#pragma unroll
                for (int g = 0; g < 2; g++)
#pragma unroll
                    for (int half = 0; half < 2; half++)
                        mma_f16(O[(pd * 2 + g) * 2 + half], ap, &bh[g][half * 2]);
            }
        }
        buf ^= 1;
    }

    // epilogue: normalize, write f16 (rn) to (B,T,C)
    float i0 = __fdividef(1.f, l0), i1 = __fdividef(1.f, l1);
    size_t base0 = ((size_t)b * TT + row0) * CC + h * DD + (lane & 3) * 2;
    size_t base1 = base0 + 8 * (size_t)CC;
    u32* oa = (u32*)ao_out;
#pragma unroll
    for (int nf = 0; nf < 8; nf++) {
        oa[(base0 + nf * 8) >> 1] = f16pair(O[nf][0] * i0, O[nf][1] * i0);
        oa[(base1 + nf * 8) >> 1] = f16pair(O[nf][2] * i1, O[nf][3] * i1);
    }
}

// ---------------------------------------------------------------------------
// Launch
// ---------------------------------------------------------------------------
extern "C" void kernel_launch(void* const* d_in, const int* in_sizes, int n_in,
                              void* d_out, int out_size)
{
    (void)in_sizes; (void)n_in; (void)out_size;
    const float* query = (const float*)d_in[0];
    const float* key   = (const float*)d_in[1];
    const float* value = (const float*)d_in[2];
    const float* mask  = (const float*)d_in[3];
    const unsigned char* kpm = (const unsigned char*)d_in[4];
    const float* Wq = (const float*)d_in[5];
    const float* bq = (const float*)d_in[6];
    const float* Wk = (const float*)d_in[7];
    const float* bk = (const float*)d_in[8];
    const float* Wv = (const float*)d_in[9];
    const float* bv = (const float*)d_in[10];
    const float* Wout = (const float*)d_in[11];
    const float* bout = (const float*)d_in[12];
    float* out = (float*)d_out;

    u16 *ph, *ao;
    int* fp;
    cudaGetSymbolAddress((void**)&ph, g_ph);
    cudaGetSymbolAddress((void**)&ao, g_ao);
    cudaGetSymbolAddress((void**)&fp, g_flags);

    const size_t PN = (size_t)BB * HH * TT * DD;

    cudaFuncSetAttribute((const void*)tc_gemm6<2, 1>,
                         cudaFuncAttributeMaxDynamicSharedMemorySize, 2 * GT5);
    cudaFuncSetAttribute((const void*)tc_gemm6<0, 2>,
                         cudaFuncAttributeMaxDynamicSharedMemorySize, 3 * GT5);
    cudaFuncSetAttribute((const void*)attn_tc4,
                         cudaFuncAttributeMaxDynamicSharedMemorySize, ATTN_SMEM4);

    cudaMemsetAsync(fp, 0, sizeof(int));
    mask_check<<<1024, 256>>>(mask, kpm);

    dim3 ggrid(CC / 128, MT / 128);   // (8, 64)
    // Q, K, V projections: single-f16 weights (1 MMA/frag), f16 outputs
    tc_gemm6<2, 1><<<ggrid, 256, 2 * GT5>>>(query, Wq, bq, SCALE_F, ph + 0 * PN);
    tc_gemm6<2, 1><<<ggrid, 256, 2 * GT5>>>(key,   Wk, bk, 1.0f,    ph + 1 * PN);
    tc_gemm6<2, 1><<<ggrid, 256, 2 * GT5>>>(value, Wv, bv, 1.0f,    ph + 2 * PN);

    attn_tc4<<<dim3(TT / 128, HH, BB), 256, ATTN_SMEM4>>>(
        mask, kpm, ph + 0 * PN, ph + 1 * PN, ph + 2 * PN, ao);

    // output projection: keep 2-term accurate (un-damped path)
    tc_gemm6<0, 2><<<ggrid, 256, 3 * GT5>>>(ao, Wout, bout, 1.0f, out);
}

// round 15
// speedup vs baseline: 3.2252x; 1.1107x over previous
#include <cuda_runtime.h>
#include <cuda_fp16.h>
#include <cstdint>

#define BB 4
#define TT 2048
#define SS 2048
#define CC 1024
#define HH 16
#define DD 64
#define SCALE_F 0.125f
#define MT (BB * TT)

typedef unsigned long long u64;
typedef unsigned int u32;
typedef unsigned short u16;

// ---------------------------------------------------------------------------
// Scratch (allocation-free rule: __device__ globals)
// ---------------------------------------------------------------------------
__device__ u16 g_xf[3][MT * CC];           // inputs q,k,v as f16
__device__ u16 g_wf[3][CC * CC];           // Wq,Wk,Wv f16
__device__ u16 g_wo_h[CC * CC];            // Wout f16 hi
__device__ u16 g_wo_l[CC * CC];            // Wout f16 lo
__device__ u16 g_ph[3][BB * HH * TT * DD]; // projected q,k,v f16 (B,H,T,D)
__device__ u16 g_ao[MT * CC];              // attn out f16 (B,T,C)
__device__ int g_flags;                    // bit0: mask nonzero, bit1: kpm any

// ---------------------------------------------------------------------------
// helpers
// ---------------------------------------------------------------------------
__device__ __forceinline__ u32 smem_u32(const void* p) {
    u32 a;
    asm("{ .reg .u64 t; cvta.to.shared.u64 t, %1; cvt.u32.u64 %0, t; }" : "=r"(a) : "l"(p));
    return a;
}
__device__ __forceinline__ void ldsm4(u32 addr, u32* r) {
    asm volatile("ldmatrix.sync.aligned.m8n8.x4.shared.b16 {%0,%1,%2,%3},[%4];"
                 : "=r"(r[0]), "=r"(r[1]), "=r"(r[2]), "=r"(r[3]) : "r"(addr));
}
__device__ __forceinline__ void ldsm4t(u32 addr, u32* r) {
    asm volatile("ldmatrix.sync.aligned.m8n8.x4.trans.shared.b16 {%0,%1,%2,%3},[%4];"
                 : "=r"(r[0]), "=r"(r[1]), "=r"(r[2]), "=r"(r[3]) : "r"(addr));
}
__device__ __forceinline__ void mma_f16(float* c, const u32* a, const u32* b) {
    asm volatile(
        "mma.sync.aligned.m16n8k16.row.col.f32.f16.f16.f32 "
        "{%0,%1,%2,%3},{%4,%5,%6,%7},{%8,%9},{%0,%1,%2,%3};"
        : "+f"(c[0]), "+f"(c[1]), "+f"(c[2]), "+f"(c[3])
        : "r"(a[0]), "r"(a[1]), "r"(a[2]), "r"(a[3]), "r"(b[0]), "r"(b[1]));
}
__device__ __forceinline__ u32 f16pair(float lo, float hi) {
    u32 r; asm("cvt.rn.f16x2.f32 %0,%1,%2;" : "=r"(r) : "f"(hi), "f"(lo)); return r;
}
__device__ __forceinline__ void h2unpack(u32 v, float& lo, float& hi) {
    asm("{.reg .b16 l,h; mov.b32 {l,h}, %2; cvt.f32.f16 %0, l; cvt.f32.f16 %1, h;}"
        : "=f"(lo), "=f"(hi) : "r"(v));
}
__device__ __forceinline__ void cpa16(u32 dst, const void* src) {
    asm volatile("cp.async.cg.shared.global [%0], [%1], 16;" :: "r"(dst), "l"(src));
}
__device__ __forceinline__ void cpa_commit() {
    asm volatile("cp.async.commit_group;" ::: "memory");
}
template <int N>
__device__ __forceinline__ void cpa_wait() {
    asm volatile("cp.async.wait_group %0;" :: "n"(N) : "memory");
}
__device__ __forceinline__ void split2_f16(float x, float y, u32& hi, u32& lo) {
    hi = f16pair(x, y);
    float hx, hy; h2unpack(hi, hx, hy);
    lo = f16pair(x - hx, y - hy);
}

// ---------------------------------------------------------------------------
// Pre-convert kernels
// ---------------------------------------------------------------------------
// fp32 -> f16 (rn), 3 tensors via grid.y (bit-identical to in-kernel cvt)
__global__ void cvt_x(const float4* __restrict__ a0, const float4* __restrict__ a1,
                      const float4* __restrict__ a2, uint2* __restrict__ out, int n4)
{
    int g = blockIdx.y;
    const float4* in = (g == 0) ? a0 : (g == 1) ? a1 : a2;
    uint2* op = out + (size_t)g * n4;
    int idx = blockIdx.x * blockDim.x + threadIdx.x;
    int stride = gridDim.x * blockDim.x;
    for (int i = idx; i < n4; i += stride) {
        float4 v = __ldg(in + i);
        op[i] = make_uint2(f16pair(v.x, v.y), f16pair(v.z, v.w));
    }
}
// weights: g<3 -> f16 single into wf[g]; g==3 -> hi/lo split into wo_h/wo_l
__global__ void cvt_w(const float4* __restrict__ w0, const float4* __restrict__ w1,
                      const float4* __restrict__ w2, const float4* __restrict__ w3,
                      uint2* __restrict__ wf, uint2* __restrict__ woh,
                      uint2* __restrict__ wol, int n4)
{
    int g = blockIdx.y;
    const float4* in = (g == 0) ? w0 : (g == 1) ? w1 : (g == 2) ? w2 : w3;
    int idx = blockIdx.x * blockDim.x + threadIdx.x;
    int stride = gridDim.x * blockDim.x;
    if (g < 3) {
        uint2* op = wf + (size_t)g * n4;
        for (int i = idx; i < n4; i += stride) {
            float4 v = __ldg(in + i);
            op[i] = make_uint2(f16pair(v.x, v.y), f16pair(v.z, v.w));
        }
    } else {
        for (int i = idx; i < n4; i += stride) {
            float4 v = __ldg(in + i);
            u32 h01, l01, h23, l23;
            split2_f16(v.x, v.y, h01, l01);
            split2_f16(v.z, v.w, h23, l23);
            woh[i] = make_uint2(h01, h23);
            wol[i] = make_uint2(l01, l23);
        }
    }
}

// ---------------------------------------------------------------------------
// Mask content check
// ---------------------------------------------------------------------------
__global__ void mask_check(const float* __restrict__ mask,
                           const unsigned char* __restrict__ kpm)
{
    int idx = blockIdx.x * blockDim.x + threadIdx.x;
    int stride = gridDim.x * blockDim.x;
    int any_m = 0;
    const float4* m4 = (const float4*)mask;
    for (int i = idx; i < (TT * SS) / 4; i += stride) {
        float4 v = __ldg(m4 + i);
        any_m |= (v.x != 0.f) | (v.y != 0.f) | (v.z != 0.f) | (v.w != 0.f);
    }
    int any_k = 0;
    const uint4* k4 = (const uint4*)kpm;
    for (int i = idx; i < (BB * SS) / 16; i += stride) {
        uint4 v = __ldg(k4 + i);
        any_k |= ((v.x | v.y | v.z | v.w) != 0u);
    }
    if (__any_sync(0xffffffffu, any_m) && (threadIdx.x & 31) == 0) atomicOr(&g_flags, 1);
    if (__any_sync(0xffffffffu, any_k) && (threadIdx.x & 31) == 0) atomicOr(&g_flags, 2);
}

// ---------------------------------------------------------------------------
// Pure-f16 cp.async 3-stage GEMM. 128x128 tile, 256 thr, 2 CTA/SM.
// MODE 1 (fused QKV): gi = blockIdx.x>>3 selects input/weight/bias; TERMS=1;
//   epilogue scatters f16 to (B,H,T,D), Q scaled.
// MODE 0 (out-proj): TERMS=2 (W pre-split hi/lo), fp32 row-major out.
// smem/stage: (1+TERMS) tiles of 128 x (CHUNK*2+16) bytes.
// ---------------------------------------------------------------------------
template <int MODE, int TERMS, int CHUNK>
__global__ __launch_bounds__(256, 2) void tc_gemm7(
    const u16* __restrict__ A0, const u16* __restrict__ A1,
    const u16* __restrict__ A2,
    const u16* __restrict__ W0, const u16* __restrict__ W1,
    const u16* __restrict__ W2,
    const float* __restrict__ b0, const float* __restrict__ b1,
    const float* __restrict__ b2,
    void* __restrict__ oa)
{
    constexpr int STR = CHUNK * 2 + 16;
    constexpr int TILE = 128 * STR;
    constexpr int STAGE = (1 + TERMS) * TILE;
    constexpr int RSLOT = CHUNK / 8;            // 16B slots per row

    extern __shared__ __align__(128) char dsm[];
    const u32 sb = smem_u32(dsm);
    const int tid = threadIdx.x;
    const int lane = tid & 31;
    const int wid = tid >> 5;
    const int wm = wid & 3;
    const int wn = wid >> 2;
    const int K = CC;
    const size_t XNs = (size_t)MT * CC;

    int gi = 0, bnx = blockIdx.x;
    const float* bias = b0;
    float scale = 1.f;
    if (MODE == 1) {
        gi = blockIdx.x >> 3;
        bnx = blockIdx.x & 7;
        bias = (gi == 0) ? b0 : (gi == 1) ? b1 : b2;
        if (gi == 0) scale = SCALE_F;
    }
    const int bm = blockIdx.y * 128, bn = bnx * 128;

    const u16* Asrc = ((gi == 0) ? A0 : (gi == 1) ? A1 : A2) + (size_t)bm * K;
    const u16* Wsrc[2];
    if (MODE == 1) {
        Wsrc[0] = ((gi == 0) ? W0 : (gi == 1) ? W1 : W2) + (size_t)bn * K;
        Wsrc[1] = Wsrc[0];
    } else {
        Wsrc[0] = W0 + (size_t)bn * K;
        Wsrc[1] = W1 + (size_t)bn * K;
    }

    const u32 aOff = (u32)((wm * 32 + (lane & 15)) * STR + (lane >> 4) * 16);
    const u32 bRow = (u32)(((lane >> 4) << 3) + (lane & 7));
    const u32 bOff = (u32)((wn * 64 + bRow) * STR + ((lane >> 3) & 1) * 16);

    float acc[2][8][4];
#pragma unroll
    for (int i = 0; i < 2; i++)
#pragma unroll
        for (int j = 0; j < 8; j++)
#pragma unroll
            for (int q = 0; q < 4; q++) acc[i][j][q] = 0.f;

    auto issue = [&](int c, int st) {
        u32 dbase = sb + st * STAGE;
        // A tile: 128*RSLOT slots
#pragma unroll
        for (int i = 0; i < (128 * RSLOT) / 256; i++) {
            int s = tid + i * 256;
            int r = s / RSLOT, j = s % RSLOT;
            cpa16(dbase + r * STR + j * 16, Asrc + (size_t)r * K + c * CHUNK + j * 8);
        }
#pragma unroll
        for (int t = 0; t < TERMS; t++) {
#pragma unroll
            for (int i = 0; i < (128 * RSLOT) / 256; i++) {
                int s = tid + i * 256;
                int r = s / RSLOT, j = s % RSLOT;
                cpa16(dbase + (1 + t) * TILE + r * STR + j * 16,
                      Wsrc[t] + (size_t)r * K + c * CHUNK + j * 8);
            }
        }
        cpa_commit();
    };

    issue(0, 0);
    issue(1, 1);
    const int nch = K / CHUNK;
    for (int c = 0; c < nch; c++) {
        if (c + 1 < nch) cpa_wait<1>(); else cpa_wait<0>();
        __syncthreads();
        if (c + 2 < nch) issue(c + 2, (c + 2) % 3);

        const u32 base = sb + (c % 3) * STAGE;
        const u32 aA = base + aOff;
        const u32 bHA = base + TILE + bOff;
        const u32 bLA = base + 2 * TILE + bOff;
#pragma unroll
        for (int ks = 0; ks < CHUNK / 16; ks++) {
            u32 ah[2][4];
#pragma unroll
            for (int mf = 0; mf < 2; mf++)
                ldsm4(aA + mf * 16 * STR + ks * 32, ah[mf]);
#pragma unroll
            for (int ng = 0; ng < 4; ng++) {
                u32 bh[4], bl[4];
                ldsm4(bHA + ng * 16 * STR + ks * 32, bh);
                if (TERMS == 2) ldsm4(bLA + ng * 16 * STR + ks * 32, bl);
#pragma unroll
                for (int half = 0; half < 2; half++) {
                    int nf = ng * 2 + half;
#pragma unroll
                    for (int mf = 0; mf < 2; mf++) {
                        mma_f16(acc[mf][nf], ah[mf], &bh[half * 2]);
                        if (TERMS == 2) mma_f16(acc[mf][nf], ah[mf], &bl[half * 2]);
                    }
                }
            }
        }
        __syncthreads();
    }

#pragma unroll
    for (int mf = 0; mf < 2; mf++) {
#pragma unroll
        for (int nf = 0; nf < 8; nf++) {
            int m = bm + wm * 32 + mf * 16 + (lane >> 2);
            int n = bn + wn * 64 + nf * 8 + (lane & 3) * 2;
            float c0 = __ldg(bias + n), c1 = __ldg(bias + n + 1);
            if (MODE == 0) {
                float* out = (float*)oa;
                *(float2*)(out + (size_t)m * CC + n) =
                    make_float2(acc[mf][nf][0] + c0, acc[mf][nf][1] + c1);
                *(float2*)(out + (size_t)(m + 8) * CC + n) =
                    make_float2(acc[mf][nf][2] + c0, acc[mf][nf][3] + c1);
            } else {
                u32* oh = (u32*)((u16*)oa + (size_t)gi * XNs);
                int h = n >> 6, d = n & (DD - 1);
                float v0 = (acc[mf][nf][0] + c0) * scale;
                float v1 = (acc[mf][nf][1] + c1) * scale;
                float v2 = (acc[mf][nf][2] + c0) * scale;
                float v3 = (acc[mf][nf][3] + c1) * scale;
                int b_ = m >> 11, t = m & (TT - 1);
                size_t idx0 = ((((size_t)b_ * HH + h) * TT + t) * DD + d) >> 1;
                int m1 = m + 8;
                int b1_ = m1 >> 11, t1 = m1 & (TT - 1);
                size_t idx1 = ((((size_t)b1_ * HH + h) * TT + t1) * DD + d) >> 1;
                oh[idx0] = f16pair(v0, v1);
                oh[idx1] = f16pair(v2, v3);
            }
        }
    }
}
#define QKV_SMEM (3 * 2 * (128 * 144))   // 110592
#define OUT_SMEM (3 * 3 * (128 * 80))    // 92160

// ---------------------------------------------------------------------------
// Tensor-core flash attention (unchanged from R14, validated).
// ---------------------------------------------------------------------------
#define AST 144
#define AKV0 18432
#define AKVB 18432
#define ATTN_SMEM4 55296

__global__ __launch_bounds__(256, 2) void attn_tc4(
    const float* __restrict__ mask, const unsigned char* __restrict__ kpm,
    const u16* __restrict__ qf, const u16* __restrict__ kf,
    const u16* __restrict__ vf, u16* __restrict__ ao_out)
{
    extern __shared__ __align__(128) char smr[];
    const u32 sb = smem_u32(smr);

    const int tid = threadIdx.x;
    const int lane = tid & 31;
    const int w = tid >> 5;
    const int tblk = blockIdx.x * 128;
    const int h = blockIdx.y, b = blockIdx.z;
    const float NEGINF = __int_as_float(0xff800000);

    const int flags = g_flags;
    const bool mflag = (flags & 1) != 0;
    const bool kflag = (flags & 2) != 0;

    const size_t baseq = (((size_t)b * HH + h) * TT + tblk) * DD;
    const size_t basekv = ((size_t)b * HH + h) * (size_t)SS * DD;

    {
        const u16* src = qf + baseq;
#pragma unroll
        for (int i = 0; i < 4; i++) {
            int s = tid + i * 256;
            int r = s >> 3, j = s & 7;
            cpa16(sb + r * AST + j * 16, src + (size_t)r * DD + j * 8);
        }
    }
    cpa_commit();

    auto issueKV = [&](int s0, int buf) {
        u32 dbase = sb + AKV0 + buf * AKVB;
        const u16* ks = kf + basekv;
        const u16* vs = vf + basekv;
#pragma unroll
        for (int i = 0; i < 2; i++) {
            int s = tid + i * 256;
            int r = s >> 3, j = s & 7;
            cpa16(dbase + r * AST + j * 16, ks + (size_t)(s0 + r) * DD + j * 8);
            cpa16(dbase + 9216 + r * AST + j * 16, vs + (size_t)(s0 + r) * DD + j * 8);
        }
        cpa_commit();
    };
    issueKV(0, 0);

    const u32 aQ = sb + (u32)((w * 16 + (lane & 15)) * AST + (lane >> 4) * 16);
    const u32 bKoff = (u32)((((lane >> 4) << 3) + (lane & 7)) * AST + ((lane >> 3) & 1) * 16);
    const u32 bVoff = (u32)((lane & 15) * AST + (lane >> 4) * 16);

    const int row0 = tblk + w * 16 + (lane >> 2);
    const float* mrow0 = mask + (size_t)row0 * SS;
    const float* mrow1 = mrow0 + 8 * (size_t)SS;

    float O[8][4];
#pragma unroll
    for (int i = 0; i < 8; i++)
#pragma unroll
        for (int j = 0; j < 4; j++) O[i][j] = 0.f;
    float l0 = 0.f, l1 = 0.f, m0 = NEGINF, m1 = NEGINF;

    int buf = 0;
    for (int c = 0; c < SS / 64; c++) {
        const int s0 = c * 64;
        cpa_wait<0>();
        __syncthreads();
        if (c + 1 < SS / 64) issueKV(s0 + 64, buf ^ 1);

        const u32 kvb = sb + AKV0 + buf * AKVB;
        const u32 bK = kvb + bKoff;
        const u32 bV = kvb + 9216 + bVoff;

        float sacc[8][4];
#pragma unroll
        for (int i = 0; i < 8; i++)
#pragma unroll
            for (int j = 0; j < 4; j++) sacc[i][j] = 0.f;
#pragma unroll
        for (int ks = 0; ks < 4; ks++) {
            u32 ahf[4];
            ldsm4(aQ + ks * 32, ahf);
#pragma unroll
            for (int pg = 0; pg < 2; pg++) {
                u32 bh[2][4];
#pragma unroll
                for (int g = 0; g < 2; g++)
                    ldsm4(bK + (pg * 2 + g) * 2304 + ks * 32, bh[g]);
#pragma unroll
                for (int g = 0; g < 2; g++)
#pragma unroll
                    for (int half = 0; half < 2; half++)
                        mma_f16(sacc[(pg * 2 + g) * 2 + half], ahf, &bh[g][half * 2]);
            }
        }

        if (kflag) {
#pragma unroll
            for (int nf = 0; nf < 8; nf++) {
                int col = s0 + nf * 8 + (lane & 3) * 2;
                float k0 = kpm[(size_t)b * SS + col] ? NEGINF : 0.f;
                float k1 = kpm[(size_t)b * SS + col + 1] ? NEGINF : 0.f;
                sacc[nf][0] += k0; sacc[nf][1] += k1;
                sacc[nf][2] += k0; sacc[nf][3] += k1;
            }
        }
        if (mflag) {
#pragma unroll
            for (int nf = 0; nf < 8; nf++) {
                int col = s0 + nf * 8 + (lane & 3) * 2;
                float2 mv0 = __ldg((const float2*)(mrow0 + col));
                float2 mv1 = __ldg((const float2*)(mrow1 + col));
                sacc[nf][0] += mv0.x; sacc[nf][1] += mv0.y;
                sacc[nf][2] += mv1.x; sacc[nf][3] += mv1.y;
            }
        }

        float cm0 = NEGINF, cm1 = NEGINF;
#pragma unroll
        for (int nf = 0; nf < 8; nf++) {
            cm0 = fmaxf(cm0, fmaxf(sacc[nf][0], sacc[nf][1]));
            cm1 = fmaxf(cm1, fmaxf(sacc[nf][2], sacc[nf][3]));
        }
        cm0 = fmaxf(cm0, __shfl_xor_sync(0xffffffffu, cm0, 1));
        cm0 = fmaxf(cm0, __shfl_xor_sync(0xffffffffu, cm0, 2));
        cm1 = fmaxf(cm1, __shfl_xor_sync(0xffffffffu, cm1, 1));
        cm1 = fmaxf(cm1, __shfl_xor_sync(0xffffffffu, cm1, 2));

        float mn0 = fmaxf(m0, cm0), mn1 = fmaxf(m1, cm1);
        float c0 = __expf(m0 - mn0), c1 = __expf(m1 - mn1);
        m0 = mn0; m1 = mn1;
        l0 *= c0; l1 *= c1;
#pragma unroll
        for (int nf = 0; nf < 8; nf++) {
            O[nf][0] *= c0; O[nf][1] *= c0;
            O[nf][2] *= c1; O[nf][3] *= c1;
        }

        u32 phi[8][2];
        float rs0 = 0.f, rs1 = 0.f;
#pragma unroll
        for (int nf = 0; nf < 8; nf++) {
            float p0 = __expf(sacc[nf][0] - mn0);
            float p1 = __expf(sacc[nf][1] - mn0);
            float p2 = __expf(sacc[nf][2] - mn1);
            float p3 = __expf(sacc[nf][3] - mn1);
            rs0 += p0 + p1; rs1 += p2 + p3;
            phi[nf][0] = f16pair(p0, p1);
            phi[nf][1] = f16pair(p2, p3);
        }
        rs0 += __shfl_xor_sync(0xffffffffu, rs0, 1);
        rs0 += __shfl_xor_sync(0xffffffffu, rs0, 2);
        rs1 += __shfl_xor_sync(0xffffffffu, rs1, 1);
        rs1 += __shfl_xor_sync(0xffffffffu, rs1, 2);
        l0 += rs0; l1 += rs1;

#pragma unroll
        for (int ks = 0; ks < 4; ks++) {
            u32 ap[4] = {phi[2 * ks][0], phi[2 * ks][1],
                         phi[2 * ks + 1][0], phi[2 * ks + 1][1]};
#pragma unroll
            for (int pd = 0; pd < 2; pd++) {
                u32 bh[2][4];
#pragma unroll
                for (int g = 0; g < 2; g++)
                    ldsm4t(bV + ks * 2304 + (pd * 2 + g) * 32, bh[g]);
#pragma unroll
                for (int g = 0; g < 2; g++)
#pragma unroll
                    for (int half = 0; half < 2; half++)
                        mma_f16(O[(pd * 2 + g) * 2 + half], ap, &bh[g][half * 2]);
            }
        }
        buf ^= 1;
    }

    float i0 = __fdividef(1.f, l0), i1 = __fdividef(1.f, l1);
    size_t base0 = ((size_t)b * TT + row0) * CC + h * DD + (lane & 3) * 2;
    size_t base1 = base0 + 8 * (size_t)CC;
    u32* oa = (u32*)ao_out;
#pragma unroll
    for (int nf = 0; nf < 8; nf++) {
        oa[(base0 + nf * 8) >> 1] = f16pair(O[nf][0] * i0, O[nf][1] * i0);
        oa[(base1 + nf * 8) >> 1] = f16pair(O[nf][2] * i1, O[nf][3] * i1);
    }
}

// ---------------------------------------------------------------------------
// Launch
// ---------------------------------------------------------------------------
extern "C" void kernel_launch(void* const* d_in, const int* in_sizes, int n_in,
                              void* d_out, int out_size)
{
    (void)in_sizes; (void)n_in; (void)out_size;
    const float* query = (const float*)d_in[0];
    const float* key   = (const float*)d_in[1];
    const float* value = (const float*)d_in[2];
    const float* mask  = (const float*)d_in[3];
    const unsigned char* kpm = (const unsigned char*)d_in[4];
    const float* Wq = (const float*)d_in[5];
    const float* bq = (const float*)d_in[6];
    const float* Wk = (const float*)d_in[7];
    const float* bk = (const float*)d_in[8];
    const float* Wv = (const float*)d_in[9];
    const float* bv = (const float*)d_in[10];
    const float* Wout = (const float*)d_in[11];
    const float* bout = (const float*)d_in[12];
    float* out = (float*)d_out;

    u16 *xf, *wf, *woh, *wol, *ph, *ao;
    int* fp;
    cudaGetSymbolAddress((void**)&xf, g_xf);
    cudaGetSymbolAddress((void**)&wf, g_wf);
    cudaGetSymbolAddress((void**)&woh, g_wo_h);
    cudaGetSymbolAddress((void**)&wol, g_wo_l);
    cudaGetSymbolAddress((void**)&ph, g_ph);
    cudaGetSymbolAddress((void**)&ao, g_ao);
    cudaGetSymbolAddress((void**)&fp, g_flags);

    const size_t XN = (size_t)MT * CC;
    const size_t WN = (size_t)CC * CC;
    const size_t PN = (size_t)BB * HH * TT * DD;

    cudaFuncSetAttribute((const void*)tc_gemm7<1, 1, 64>,
                         cudaFuncAttributeMaxDynamicSharedMemorySize, QKV_SMEM);
    cudaFuncSetAttribute((const void*)tc_gemm7<0, 2, 32>,
                         cudaFuncAttributeMaxDynamicSharedMemorySize, OUT_SMEM);
    cudaFuncSetAttribute((const void*)attn_tc4,
                         cudaFuncAttributeMaxDynamicSharedMemorySize, ATTN_SMEM4);

    cudaMemsetAsync(fp, 0, sizeof(int));
    mask_check<<<1024, 256>>>(mask, kpm);

    // pre-convert inputs + weights (bit-identical rounding to prior in-kernel cvt)
    cvt_x<<<dim3(1024, 3), 256>>>((const float4*)query, (const float4*)key,
                                  (const float4*)value, (uint2*)xf, (int)(XN / 4));
    cvt_w<<<dim3(512, 4), 256>>>((const float4*)Wq, (const float4*)Wk,
                                 (const float4*)Wv, (const float4*)Wout,
                                 (uint2*)wf, (uint2*)woh, (uint2*)wol, (int)(WN / 4));

    // fused QKV projections (1536 CTAs, 5.2 waves)
    tc_gemm7<1, 1, 64><<<dim3(24, MT / 128), 256, QKV_SMEM>>>(
        xf + 0 * XN, xf + 1 * XN, xf + 2 * XN,
        wf + 0 * WN, wf + 1 * WN, wf + 2 * WN,
        bq, bk, bv, ph);

    attn_tc4<<<dim3(TT / 128, HH, BB), 256, ATTN_SMEM4>>>(
        mask, kpm, ph + 0 * PN, ph + 1 * PN, ph + 2 * PN, ao);

    // output projection: 2-term accurate, pre-split Wout
    tc_gemm7<0, 2, 32><<<dim3(8, MT / 128), 256, OUT_SMEM>>>(
        ao, ao, ao, woh, wol, wol, bout, bout, bout, out);
}

// round 16
// speedup vs baseline: 3.7609x; 1.1661x over previous
#include <cuda_runtime.h>
#include <cuda_fp16.h>
#include <cstdint>

#define BB 4
#define TT 2048
#define SS 2048
#define CC 1024
#define HH 16
#define DD 64
#define SCALE_F 0.125f
#define MT (BB * TT)

typedef unsigned long long u64;
typedef unsigned int u32;
typedef unsigned short u16;

// ---------------------------------------------------------------------------
// Scratch (allocation-free rule: __device__ globals)
// ---------------------------------------------------------------------------
__device__ u16 g_xf[3][MT * CC];           // inputs q,k,v as f16
__device__ u16 g_wf[4][CC * CC];           // Wq,Wk,Wv,Wout f16
__device__ u16 g_ph[3][BB * HH * TT * DD]; // projected q,k,v f16 (B,H,T,D)
__device__ u16 g_ao[MT * CC];              // attn out f16 (B,T,C)
__device__ int g_flags;                    // bit0: mask nonzero, bit1: kpm any

// ---------------------------------------------------------------------------
// helpers
// ---------------------------------------------------------------------------
__device__ __forceinline__ u32 smem_u32(const void* p) {
    u32 a;
    asm("{ .reg .u64 t; cvta.to.shared.u64 t, %1; cvt.u32.u64 %0, t; }" : "=r"(a) : "l"(p));
    return a;
}
__device__ __forceinline__ void ldsm4(u32 addr, u32* r) {
    asm volatile("ldmatrix.sync.aligned.m8n8.x4.shared.b16 {%0,%1,%2,%3},[%4];"
                 : "=r"(r[0]), "=r"(r[1]), "=r"(r[2]), "=r"(r[3]) : "r"(addr));
}
__device__ __forceinline__ void ldsm4t(u32 addr, u32* r) {
    asm volatile("ldmatrix.sync.aligned.m8n8.x4.trans.shared.b16 {%0,%1,%2,%3},[%4];"
                 : "=r"(r[0]), "=r"(r[1]), "=r"(r[2]), "=r"(r[3]) : "r"(addr));
}
__device__ __forceinline__ void mma_f16(float* c, const u32* a, const u32* b) {
    asm volatile(
        "mma.sync.aligned.m16n8k16.row.col.f32.f16.f16.f32 "
        "{%0,%1,%2,%3},{%4,%5,%6,%7},{%8,%9},{%0,%1,%2,%3};"
        : "+f"(c[0]), "+f"(c[1]), "+f"(c[2]), "+f"(c[3])
        : "r"(a[0]), "r"(a[1]), "r"(a[2]), "r"(a[3]), "r"(b[0]), "r"(b[1]));
}
__device__ __forceinline__ u32 f16pair(float lo, float hi) {
    u32 r; asm("cvt.rn.f16x2.f32 %0,%1,%2;" : "=r"(r) : "f"(hi), "f"(lo)); return r;
}
__device__ __forceinline__ void cpa16(u32 dst, const void* src) {
    asm volatile("cp.async.cg.shared.global [%0], [%1], 16;" :: "r"(dst), "l"(src));
}
__device__ __forceinline__ void cpa_commit() {
    asm volatile("cp.async.commit_group;" ::: "memory");
}
template <int N>
__device__ __forceinline__ void cpa_wait() {
    asm volatile("cp.async.wait_group %0;" :: "n"(N) : "memory");
}

// ---------------------------------------------------------------------------
// Pre-convert kernels (fp32 -> f16 rn; bit-identical to prior in-kernel cvt)
// ---------------------------------------------------------------------------
__global__ void cvt_x(const float4* __restrict__ a0, const float4* __restrict__ a1,
                      const float4* __restrict__ a2, uint2* __restrict__ out, int n4)
{
    int g = blockIdx.y;
    const float4* in = (g == 0) ? a0 : (g == 1) ? a1 : a2;
    uint2* op = out + (size_t)g * n4;
    int idx = blockIdx.x * blockDim.x + threadIdx.x;
    int stride = gridDim.x * blockDim.x;
    for (int i = idx; i < n4; i += stride) {
        float4 v = __ldg(in + i);
        op[i] = make_uint2(f16pair(v.x, v.y), f16pair(v.z, v.w));
    }
}
__global__ void cvt_w(const float4* __restrict__ w0, const float4* __restrict__ w1,
                      const float4* __restrict__ w2, const float4* __restrict__ w3,
                      uint2* __restrict__ wf, int n4)
{
    int g = blockIdx.y;
    const float4* in = (g == 0) ? w0 : (g == 1) ? w1 : (g == 2) ? w2 : w3;
    uint2* op = wf + (size_t)g * n4;
    int idx = blockIdx.x * blockDim.x + threadIdx.x;
    int stride = gridDim.x * blockDim.x;
    for (int i = idx; i < n4; i += stride) {
        float4 v = __ldg(in + i);
        op[i] = make_uint2(f16pair(v.x, v.y), f16pair(v.z, v.w));
    }
}

// ---------------------------------------------------------------------------
// Mask content check
// ---------------------------------------------------------------------------
__global__ void mask_check(const float* __restrict__ mask,
                           const unsigned char* __restrict__ kpm)
{
    int idx = blockIdx.x * blockDim.x + threadIdx.x;
    int stride = gridDim.x * blockDim.x;
    int any_m = 0;
    const float4* m4 = (const float4*)mask;
    for (int i = idx; i < (TT * SS) / 4; i += stride) {
        float4 v = __ldg(m4 + i);
        any_m |= (v.x != 0.f) | (v.y != 0.f) | (v.z != 0.f) | (v.w != 0.f);
    }
    int any_k = 0;
    const uint4* k4 = (const uint4*)kpm;
    for (int i = idx; i < (BB * SS) / 16; i += stride) {
        uint4 v = __ldg(k4 + i);
        any_k |= ((v.x | v.y | v.z | v.w) != 0u);
    }
    if (__any_sync(0xffffffffu, any_m) && (threadIdx.x & 31) == 0) atomicOr(&g_flags, 1);
    if (__any_sync(0xffffffffu, any_k) && (threadIdx.x & 31) == 0) atomicOr(&g_flags, 2);
}

// ---------------------------------------------------------------------------
// Pure-f16 cp.async 3-stage GEMM. 128x128 tile, 256 thr, 2 CTA/SM.
// MODE 1 (fused QKV): gi = blockIdx.x>>3 selects input/weight/bias;
//   epilogue scatters f16 to (B,H,T,D), Q scaled.
// MODE 0 (out-proj): f16 A and W, fp32 row-major out.
// smem/stage: 2 tiles of 128 x 144 bytes.
// ---------------------------------------------------------------------------
#define CHUNK7 64
#define STR7 144
#define TILE7 (128 * STR7)        // 18432
#define STAGE7 (2 * TILE7)        // 36864
#define GEMM7_SMEM (3 * STAGE7)   // 110592

template <int MODE>
__global__ __launch_bounds__(256, 2) void tc_gemm7(
    const u16* __restrict__ A0, const u16* __restrict__ A1,
    const u16* __restrict__ A2,
    const u16* __restrict__ W0, const u16* __restrict__ W1,
    const u16* __restrict__ W2,
    const float* __restrict__ b0, const float* __restrict__ b1,
    const float* __restrict__ b2,
    void* __restrict__ oa)
{
    extern __shared__ __align__(128) char dsm[];
    const u32 sb = smem_u32(dsm);
    const int tid = threadIdx.x;
    const int lane = tid & 31;
    const int wid = tid >> 5;
    const int wm = wid & 3;
    const int wn = wid >> 2;
    const int K = CC;
    const size_t XNs = (size_t)MT * CC;

    int gi = 0, bnx = blockIdx.x;
    const float* bias = b0;
    float scale = 1.f;
    if (MODE == 1) {
        gi = blockIdx.x >> 3;
        bnx = blockIdx.x & 7;
        bias = (gi == 0) ? b0 : (gi == 1) ? b1 : b2;
        if (gi == 0) scale = SCALE_F;
    }
    const int bm = blockIdx.y * 128, bn = bnx * 128;

    const u16* Asrc = ((gi == 0) ? A0 : (gi == 1) ? A1 : A2) + (size_t)bm * K;
    const u16* Wsrc = ((MODE == 1)
                       ? ((gi == 0) ? W0 : (gi == 1) ? W1 : W2)
                       : W0) + (size_t)bn * K;

    const u32 aOff = (u32)((wm * 32 + (lane & 15)) * STR7 + (lane >> 4) * 16);
    const u32 bRow = (u32)(((lane >> 4) << 3) + (lane & 7));
    const u32 bOff = (u32)((wn * 64 + bRow) * STR7 + ((lane >> 3) & 1) * 16);

    float acc[2][8][4];
#pragma unroll
    for (int i = 0; i < 2; i++)
#pragma unroll
        for (int j = 0; j < 8; j++)
#pragma unroll
            for (int q = 0; q < 4; q++) acc[i][j][q] = 0.f;

    auto issue = [&](int c, int st) {
        u32 dbase = sb + st * STAGE7;
#pragma unroll
        for (int i = 0; i < 4; i++) {          // 1024 slots, A tile
            int s = tid + i * 256;
            int r = s >> 3, j = s & 7;
            cpa16(dbase + r * STR7 + j * 16, Asrc + (size_t)r * K + c * CHUNK7 + j * 8);
        }
#pragma unroll
        for (int i = 0; i < 4; i++) {          // 1024 slots, W tile
            int s = tid + i * 256;
            int r = s >> 3, j = s & 7;
            cpa16(dbase + TILE7 + r * STR7 + j * 16,
                  Wsrc + (size_t)r * K + c * CHUNK7 + j * 8);
        }
        cpa_commit();
    };

    issue(0, 0);
    issue(1, 1);
    const int nch = K / CHUNK7;
    for (int c = 0; c < nch; c++) {
        if (c + 1 < nch) cpa_wait<1>(); else cpa_wait<0>();
        __syncthreads();
        if (c + 2 < nch) issue(c + 2, (c + 2) % 3);

        const u32 base = sb + (c % 3) * STAGE7;
        const u32 aA = base + aOff;
        const u32 bA = base + TILE7 + bOff;
#pragma unroll
        for (int ks = 0; ks < 4; ks++) {
            u32 ah[2][4];
#pragma unroll
            for (int mf = 0; mf < 2; mf++)
                ldsm4(aA + mf * 16 * STR7 + ks * 32, ah[mf]);
#pragma unroll
            for (int ng = 0; ng < 4; ng++) {
                u32 bh[4];
                ldsm4(bA + ng * 16 * STR7 + ks * 32, bh);
#pragma unroll
                for (int half = 0; half < 2; half++) {
                    int nf = ng * 2 + half;
#pragma unroll
                    for (int mf = 0; mf < 2; mf++)
                        mma_f16(acc[mf][nf], ah[mf], &bh[half * 2]);
                }
            }
        }
        __syncthreads();
    }

#pragma unroll
    for (int mf = 0; mf < 2; mf++) {
#pragma unroll
        for (int nf = 0; nf < 8; nf++) {
            int m = bm + wm * 32 + mf * 16 + (lane >> 2);
            int n = bn + wn * 64 + nf * 8 + (lane & 3) * 2;
            float c0 = __ldg(bias + n), c1 = __ldg(bias + n + 1);
            if (MODE == 0) {
                float* out = (float*)oa;
                *(float2*)(out + (size_t)m * CC + n) =
                    make_float2(acc[mf][nf][0] + c0, acc[mf][nf][1] + c1);
                *(float2*)(out + (size_t)(m + 8) * CC + n) =
                    make_float2(acc[mf][nf][2] + c0, acc[mf][nf][3] + c1);
            } else {
                u32* oh = (u32*)((u16*)oa + (size_t)gi * XNs);
                int h = n >> 6, d = n & (DD - 1);
                float v0 = (acc[mf][nf][0] + c0) * scale;
                float v1 = (acc[mf][nf][1] + c1) * scale;
                float v2 = (acc[mf][nf][2] + c0) * scale;
                float v3 = (acc[mf][nf][3] + c1) * scale;
                int b_ = m >> 11, t = m & (TT - 1);
                size_t idx0 = ((((size_t)b_ * HH + h) * TT + t) * DD + d) >> 1;
                int m1 = m + 8;
                int b1_ = m1 >> 11, t1 = m1 & (TT - 1);
                size_t idx1 = ((((size_t)b1_ * HH + h) * TT + t1) * DD + d) >> 1;
                oh[idx0] = f16pair(v0, v1);
                oh[idx1] = f16pair(v2, v3);
            }
        }
    }
}

// ---------------------------------------------------------------------------
// Tensor-core flash attention, all-single-f16 operands.
// Fast path (no masks): no max-tracking (scores bounded, fp32-safe),
// no O-rescale, no shfl-max. Full online-softmax path when masks present.
// ---------------------------------------------------------------------------
#define AST 144
#define AKV0 18432
#define AKVB 18432
#define ATTN_SMEM4 55296

__global__ __launch_bounds__(256, 2) void attn_tc4(
    const float* __restrict__ mask, const unsigned char* __restrict__ kpm,
    const u16* __restrict__ qf, const u16* __restrict__ kf,
    const u16* __restrict__ vf, u16* __restrict__ ao_out)
{
    extern __shared__ __align__(128) char smr[];
    const u32 sb = smem_u32(smr);

    const int tid = threadIdx.x;
    const int lane = tid & 31;
    const int w = tid >> 5;
    const int tblk = blockIdx.x * 128;
    const int h = blockIdx.y, b = blockIdx.z;
    const float NEGINF = __int_as_float(0xff800000);

    const int flags = g_flags;
    const bool mflag = (flags & 1) != 0;
    const bool kflag = (flags & 2) != 0;
    const bool anyflag = mflag || kflag;

    const size_t baseq = (((size_t)b * HH + h) * TT + tblk) * DD;
    const size_t basekv = ((size_t)b * HH + h) * (size_t)SS * DD;

    {
        const u16* src = qf + baseq;
#pragma unroll
        for (int i = 0; i < 4; i++) {
            int s = tid + i * 256;
            int r = s >> 3, j = s & 7;
            cpa16(sb + r * AST + j * 16, src + (size_t)r * DD + j * 8);
        }
    }
    cpa_commit();

    auto issueKV = [&](int s0, int buf) {
        u32 dbase = sb + AKV0 + buf * AKVB;
        const u16* ks = kf + basekv;
        const u16* vs = vf + basekv;
#pragma unroll
        for (int i = 0; i < 2; i++) {
            int s = tid + i * 256;
            int r = s >> 3, j = s & 7;
            cpa16(dbase + r * AST + j * 16, ks + (size_t)(s0 + r) * DD + j * 8);
            cpa16(dbase + 9216 + r * AST + j * 16, vs + (size_t)(s0 + r) * DD + j * 8);
        }
        cpa_commit();
    };
    issueKV(0, 0);

    const u32 aQ = sb + (u32)((w * 16 + (lane & 15)) * AST + (lane >> 4) * 16);
    const u32 bKoff = (u32)((((lane >> 4) << 3) + (lane & 7)) * AST + ((lane >> 3) & 1) * 16);
    const u32 bVoff = (u32)((lane & 15) * AST + (lane >> 4) * 16);

    const int row0 = tblk + w * 16 + (lane >> 2);
    const float* mrow0 = mask + (size_t)row0 * SS;
    const float* mrow1 = mrow0 + 8 * (size_t)SS;

    float O[8][4];
#pragma unroll
    for (int i = 0; i < 8; i++)
#pragma unroll
        for (int j = 0; j < 4; j++) O[i][j] = 0.f;
    float l0 = 0.f, l1 = 0.f, m0 = NEGINF, m1 = NEGINF;

    int buf = 0;
    for (int c = 0; c < SS / 64; c++) {
        const int s0 = c * 64;
        cpa_wait<0>();
        __syncthreads();
        if (c + 1 < SS / 64) issueKV(s0 + 64, buf ^ 1);

        const u32 kvb = sb + AKV0 + buf * AKVB;
        const u32 bK = kvb + bKoff;
        const u32 bV = kvb + 9216 + bVoff;

        float sacc[8][4];
#pragma unroll
        for (int i = 0; i < 8; i++)
#pragma unroll
            for (int j = 0; j < 4; j++) sacc[i][j] = 0.f;
#pragma unroll
        for (int ks = 0; ks < 4; ks++) {
            u32 ahf[4];
            ldsm4(aQ + ks * 32, ahf);
#pragma unroll
            for (int pg = 0; pg < 2; pg++) {
                u32 bh[2][4];
#pragma unroll
                for (int g = 0; g < 2; g++)
                    ldsm4(bK + (pg * 2 + g) * 2304 + ks * 32, bh[g]);
#pragma unroll
                for (int g = 0; g < 2; g++)
#pragma unroll
                    for (int half = 0; half < 2; half++)
                        mma_f16(sacc[(pg * 2 + g) * 2 + half], ahf, &bh[g][half * 2]);
            }
        }

        float mn0 = 0.f, mn1 = 0.f;
        if (anyflag) {
            if (kflag) {
#pragma unroll
                for (int nf = 0; nf < 8; nf++) {
                    int col = s0 + nf * 8 + (lane & 3) * 2;
                    float k0 = kpm[(size_t)b * SS + col] ? NEGINF : 0.f;
                    float k1 = kpm[(size_t)b * SS + col + 1] ? NEGINF : 0.f;
                    sacc[nf][0] += k0; sacc[nf][1] += k1;
                    sacc[nf][2] += k0; sacc[nf][3] += k1;
                }
            }
            if (mflag) {
#pragma unroll
                for (int nf = 0; nf < 8; nf++) {
                    int col = s0 + nf * 8 + (lane & 3) * 2;
                    float2 mv0 = __ldg((const float2*)(mrow0 + col));
                    float2 mv1 = __ldg((const float2*)(mrow1 + col));
                    sacc[nf][0] += mv0.x; sacc[nf][1] += mv0.y;
                    sacc[nf][2] += mv1.x; sacc[nf][3] += mv1.y;
                }
            }
            float cm0 = NEGINF, cm1 = NEGINF;
#pragma unroll
            for (int nf = 0; nf < 8; nf++) {
                cm0 = fmaxf(cm0, fmaxf(sacc[nf][0], sacc[nf][1]));
                cm1 = fmaxf(cm1, fmaxf(sacc[nf][2], sacc[nf][3]));
            }
            cm0 = fmaxf(cm0, __shfl_xor_sync(0xffffffffu, cm0, 1));
            cm0 = fmaxf(cm0, __shfl_xor_sync(0xffffffffu, cm0, 2));
            cm1 = fmaxf(cm1, __shfl_xor_sync(0xffffffffu, cm1, 1));
            cm1 = fmaxf(cm1, __shfl_xor_sync(0xffffffffu, cm1, 2));
            mn0 = fmaxf(m0, cm0); mn1 = fmaxf(m1, cm1);
            float c0 = __expf(m0 - mn0), c1 = __expf(m1 - mn1);
            m0 = mn0; m1 = mn1;
            l0 *= c0; l1 *= c1;
#pragma unroll
            for (int nf = 0; nf < 8; nf++) {
                O[nf][0] *= c0; O[nf][1] *= c0;
                O[nf][2] *= c1; O[nf][3] *= c1;
            }
        }

        u32 phi[8][2];
        float rs0 = 0.f, rs1 = 0.f;
#pragma unroll
        for (int nf = 0; nf < 8; nf++) {
            float p0 = __expf(sacc[nf][0] - mn0);
            float p1 = __expf(sacc[nf][1] - mn0);
            float p2 = __expf(sacc[nf][2] - mn1);
            float p3 = __expf(sacc[nf][3] - mn1);
            rs0 += p0 + p1; rs1 += p2 + p3;
            phi[nf][0] = f16pair(p0, p1);
            phi[nf][1] = f16pair(p2, p3);
        }
        rs0 += __shfl_xor_sync(0xffffffffu, rs0, 1);
        rs0 += __shfl_xor_sync(0xffffffffu, rs0, 2);
        rs1 += __shfl_xor_sync(0xffffffffu, rs1, 1);
        rs1 += __shfl_xor_sync(0xffffffffu, rs1, 2);
        l0 += rs0; l1 += rs1;

#pragma unroll
        for (int ks = 0; ks < 4; ks++) {
            u32 ap[4] = {phi[2 * ks][0], phi[2 * ks][1],
                         phi[2 * ks + 1][0], phi[2 * ks + 1][1]};
#pragma unroll
            for (int pd = 0; pd < 2; pd++) {
                u32 bh[2][4];
#pragma unroll
                for (int g = 0; g < 2; g++)
                    ldsm4t(bV + ks * 2304 + (pd * 2 + g) * 32, bh[g]);
#pragma unroll
                for (int g = 0; g < 2; g++)
#pragma unroll
                    for (int half = 0; half < 2; half++)
                        mma_f16(O[(pd * 2 + g) * 2 + half], ap, &bh[g][half * 2]);
            }
        }
        buf ^= 1;
    }

    float i0 = __fdividef(1.f, l0), i1 = __fdividef(1.f, l1);
    size_t base0 = ((size_t)b * TT + row0) * CC + h * DD + (lane & 3) * 2;
    size_t base1 = base0 + 8 * (size_t)CC;
    u32* oa = (u32*)ao_out;
#pragma unroll
    for (int nf = 0; nf < 8; nf++) {
        oa[(base0 + nf * 8) >> 1] = f16pair(O[nf][0] * i0, O[nf][1] * i0);
        oa[(base1 + nf * 8) >> 1] = f16pair(O[nf][2] * i1, O[nf][3] * i1);
    }
}

// ---------------------------------------------------------------------------
// Launch
// ---------------------------------------------------------------------------
extern "C" void kernel_launch(void* const* d_in, const int* in_sizes, int n_in,
                              void* d_out, int out_size)
{
    (void)in_sizes; (void)n_in; (void)out_size;
    const float* query = (const float*)d_in[0];
    const float* key   = (const float*)d_in[1];
    const float* value = (const float*)d_in[2];
    const float* mask  = (const float*)d_in[3];
    const unsigned char* kpm = (const unsigned char*)d_in[4];
    const float* Wq = (const float*)d_in[5];
    const float* bq = (const float*)d_in[6];
    const float* Wk = (const float*)d_in[7];
    const float* bk = (const float*)d_in[8];
    const float* Wv = (const float*)d_in[9];
    const float* bv = (const float*)d_in[10];
    const float* Wout = (const float*)d_in[11];
    const float* bout = (const float*)d_in[12];
    float* out = (float*)d_out;

    u16 *xf, *wf, *ph, *ao;
    int* fp;
    cudaGetSymbolAddress((void**)&xf, g_xf);
    cudaGetSymbolAddress((void**)&wf, g_wf);
    cudaGetSymbolAddress((void**)&ph, g_ph);
    cudaGetSymbolAddress((void**)&ao, g_ao);
    cudaGetSymbolAddress((void**)&fp, g_flags);

    const size_t XN = (size_t)MT * CC;
    const size_t WN = (size_t)CC * CC;
    const size_t PN = (size_t)BB * HH * TT * DD;

    cudaFuncSetAttribute((const void*)tc_gemm7<1>,
                         cudaFuncAttributeMaxDynamicSharedMemorySize, GEMM7_SMEM);
    cudaFuncSetAttribute((const void*)tc_gemm7<0>,
                         cudaFuncAttributeMaxDynamicSharedMemorySize, GEMM7_SMEM);
    cudaFuncSetAttribute((const void*)attn_tc4,
                         cudaFuncAttributeMaxDynamicSharedMemorySize, ATTN_SMEM4);

    cudaMemsetAsync(fp, 0, sizeof(int));
    mask_check<<<1024, 256>>>(mask, kpm);

    cvt_x<<<dim3(1024, 3), 256>>>((const float4*)query, (const float4*)key,
                                  (const float4*)value, (uint2*)xf, (int)(XN / 4));
    cvt_w<<<dim3(512, 4), 256>>>((const float4*)Wq, (const float4*)Wk,
                                 (const float4*)Wv, (const float4*)Wout,
                                 (uint2*)wf, (int)(WN / 4));

    // fused QKV projections
    tc_gemm7<1><<<dim3(24, MT / 128), 256, GEMM7_SMEM>>>(
        xf + 0 * XN, xf + 1 * XN, xf + 2 * XN,
        wf + 0 * WN, wf + 1 * WN, wf + 2 * WN,
        bq, bk, bv, ph);

    attn_tc4<<<dim3(TT / 128, HH, BB), 256, ATTN_SMEM4>>>(
        mask, kpm, ph + 0 * PN, ph + 1 * PN, ph + 2 * PN, ao);

    // output projection (single-f16 Wout, 1 MMA/frag)
    tc_gemm7<0><<<dim3(8, MT / 128), 256, GEMM7_SMEM>>>(
        ao, ao, ao, wf + 3 * WN, wf + 3 * WN, wf + 3 * WN,
        bout, bout, bout, out);
}